// round 12
// baseline (speedup 1.0000x reference)
#include <cuda_runtime.h>
#include <math.h>

#define NIN   12
#define NOUT  4
#define NHID  512
#define NU    40
#define NB    108
#define NINEQ 148
#define BATCH 4096
#define IPM_ITERS 20
#define SIGMA 0.1f
#define BIGF  1000000000.0f
#define EPSF  0.0001f

#define WPB   8
#define PPW   2
#define PPC   (WPB * PPW)
#define NTH   (32 * WPB)

// shared scalar layout (floats)
#define SQ_OFF 0                // 40*44 = 1760
#define SB_OFF 1760             // 108*44 = 4752
#define SH_OFF 6512             // 148 -> pad to 6672
#define PR_OFF 6672

// per-pair packed layout (u64 units)
#define H2_OFF   0              // 820 packed lower triangle
#define D2_OFF   820            // 148
#define V2_OFF   968            // 148
#define U2_OFF   1116           // 40
#define RHS2_OFF 1156           // 40
#define DU2_OFF  1196           // 40
#define LDI2_OFF 1236           // 40
#define P2_OFF   1276           // 40
#define PSTRIDE_U64 1320

#define SMEM_FLOATS (PR_OFF + WPB * PSTRIDE_U64 * 2)
#define SMEM_BYTES  (SMEM_FLOATS * 4)

typedef unsigned long long u64;

__device__ __forceinline__ u64 pk2(float lo, float hi) {
    u64 r; asm("mov.b64 %0,{%1,%2};" : "=l"(r) : "f"(lo), "f"(hi)); return r;
}
__device__ __forceinline__ void upk2(u64 v, float& lo, float& hi) {
    asm("mov.b64 {%0,%1},%2;" : "=f"(lo), "=f"(hi) : "l"(v));
}
__device__ __forceinline__ u64 rep2(float x) { return pk2(x, x); }
__device__ __forceinline__ u64 fma2(u64 a, u64 b, u64 c) {
    u64 d; asm("fma.rn.f32x2 %0,%1,%2,%3;" : "=l"(d) : "l"(a), "l"(b), "l"(c)); return d;
}
__device__ __forceinline__ u64 mul2(u64 a, u64 b) {
    u64 d; asm("mul.rn.f32x2 %0,%1,%2;" : "=l"(d) : "l"(a), "l"(b)); return d;
}
__device__ __forceinline__ u64 add2(u64 a, u64 b) {
    u64 d; asm("add.rn.f32x2 %0,%1,%2;" : "=l"(d) : "l"(a), "l"(b)); return d;
}
__device__ __forceinline__ u64 neg2(u64 a) { return a ^ 0x8000000080000000ULL; }

__device__ float g_Q[NU * NU];
__device__ float g_B[NB * NU];
__device__ float g_h[NINEQ];
__device__ float g_p[BATCH * NU];

__device__ __forceinline__ float lrelu(float x) { return x > 0.f ? x : 0.01f * x; }
__device__ __forceinline__ int toff(int r) { return (r * (r + 1)) >> 1; }

// ================= setup =================
__global__ void setup_kernel(const float* __restrict__ L, const float* __restrict__ LP,
                             const float* __restrict__ LR, const float* __restrict__ A,
                             const float* __restrict__ Bm, const float* __restrict__ u0,
                             const float* __restrict__ s0) {
    __shared__ float sQx[144], sP[144], sR[16], sBp[9 * 48];
    __shared__ float sBh[NB * NU];
    __shared__ float sM[NB * NU];
    int tid = threadIdx.x;
    const int NTs = 128;

    for (int idx = tid; idx < 144; idx += NTs) {
        int i = idx / 12, j = idx % 12;
        int mn = i < j ? i : j;
        float a = 0.f, b = 0.f;
        for (int k = 0; k <= mn; k++) {
            a += L[i * 12 + k] * L[j * 12 + k];
            b += LP[i * 12 + k] * LP[j * 12 + k];
        }
        sQx[idx] = a + (i == j ? EPSF : 0.f);
        sP[idx]  = b + (i == j ? EPSF : 0.f);
    }
    for (int idx = tid; idx < 16; idx += NTs) {
        int i = idx / 4, j = idx % 4;
        int mn = i < j ? i : j;
        float a = 0.f;
        for (int k = 0; k <= mn; k++) a += LR[i * 4 + k] * LR[j * 4 + k];
        sR[idx] = a + (i == j ? EPSF : 0.f);
    }
    if (tid < 48) sBp[tid] = Bm[tid];
    __syncthreads();

    for (int m = 1; m < 9; m++) {
        if (tid < 48) {
            int i = tid / 4, o = tid % 4;
            float v = 0.f;
            for (int k = 0; k < 12; k++) v += A[i * 12 + k] * sBp[(m - 1) * 48 + k * 4 + o];
            sBp[m * 48 + tid] = v;
        }
        __syncthreads();
    }

    for (int idx = tid; idx < NB * NU; idx += NTs) {
        int row = idx / NU, col = idx % NU;
        int rb = row / 12, i = row % 12, cb = col / 4, o = col % 4;
        float v = (cb <= rb) ? sBp[(rb - cb) * 48 + i * 4 + o] : 0.f;
        sBh[idx] = v;
        g_B[idx] = v;
    }
    __syncthreads();

    for (int idx = tid; idx < NB * NU; idx += NTs) {
        int row = idx / NU, col = idx % NU;
        int rb = row / 12, i = row % 12;
        const float* Qd = (rb < 8) ? sQx : sP;
        float a = 0.f;
        for (int k = 0; k < 12; k++) a += Qd[i * 12 + k] * sBh[(rb * 12 + k) * NU + col];
        sM[idx] = a;
    }
    __syncthreads();

    for (int idx = tid; idx < NU * NU; idx += NTs) {
        int a_ = idx / NU, b_ = idx % NU;
        float v = (a_ / 4 == b_ / 4) ? sR[(a_ % 4) * 4 + (b_ % 4)] : 0.f;
        for (int r = 0; r < NB; r++) v += sBh[r * NU + a_] * sM[r * NU + b_];
        g_Q[idx] = v;
    }

    for (int j = tid; j < NINEQ; j += NTs) {
        float v = s0[j];
        if (j < NU) v += u0[j];
        else {
            for (int i = 0; i < NU; i++) v += sBh[(j - NU) * NU + i] * u0[i];
        }
        g_h[j] = v;
    }
}

// ================= MLP =================
__global__ void mlp_kernel(const float* __restrict__ x, const float* __restrict__ W1,
                           const float* __restrict__ b1, const float* __restrict__ W2,
                           const float* __restrict__ b2) {
    __shared__ float hbuf[4][NHID];
    int warp = threadIdx.x >> 5, lane = threadIdx.x & 31;
    int row = blockIdx.x * 4 + warp;

    float xr[NIN];
#pragma unroll
    for (int c = 0; c < NIN; c++) xr[c] = x[row * NIN + c];

#pragma unroll
    for (int t = 0; t < NHID / 32; t++) {
        int j = lane + 32 * t;
        const float* w = W1 + j * NIN;
        float acc = b1[j];
#pragma unroll
        for (int c = 0; c < NIN; c++) acc += w[c] * xr[c];
        hbuf[warp][j] = lrelu(acc);
    }
    __syncwarp();

    for (int k = 0; k < NU; k++) {
        const float* w = W2 + k * NHID;
        float acc = 0.f;
#pragma unroll
        for (int t = 0; t < NHID / 32; t++) {
            int j = lane + 32 * t;
            acc += w[j] * hbuf[warp][j];
        }
#pragma unroll
        for (int o = 16; o; o >>= 1) acc += __shfl_xor_sync(0xffffffffu, acc, o);
        if (lane == 0) g_p[row * NU + k] = lrelu(acc + b2[k]);
    }
}

// ================= IPM: two problems per warp, f32x2, rp recurrence =================
__global__ void __launch_bounds__(NTH, 2) ipm_kernel(float* __restrict__ out) {
    extern __shared__ float sm[];
    float* sQ  = sm + SQ_OFF;    // stride 44
    float* sB  = sm + SB_OFF;    // stride 44
    float* sh_ = sm + SH_OFF;

    int tid = threadIdx.x;
    int lane = tid & 31, wid = tid >> 5;

    for (int idx = tid; idx < NU * NU; idx += NTH) sQ[(idx / NU) * 44 + idx % NU] = g_Q[idx];
    for (int idx = tid; idx < NB * NU; idx += NTH) sB[(idx / NU) * 44 + idx % NU] = g_B[idx];
    for (int idx = tid; idx < NINEQ; idx += NTH) sh_[idx] = g_h[idx];
    __syncthreads();

    int pb = blockIdx.x * PPC + wid * PPW;
    u64* PR = (u64*)(sm + PR_OFF) + wid * PSTRIDE_U64;
    u64* pH2  = PR + H2_OFF;
    u64* pD2  = PR + D2_OFF;
    u64* pV2  = PR + V2_OFF;
    u64* pU2  = PR + U2_OFF;
    u64* pR2  = PR + RHS2_OFF;
    u64* pDU2 = PR + DU2_OFF;
    u64* pLi2 = PR + LDI2_OFF;
    u64* pP2  = PR + P2_OFF;

    if (lane < NU) {
        pU2[lane] = 0ULL;
        pP2[lane] = pk2(g_p[pb * NU + lane], g_p[(pb + 1) * NU + lane]);
    }
    if (lane < 8) {
        pU2[32 + lane] = 0ULL;
        pP2[32 + lane] = pk2(g_p[pb * NU + 32 + lane], g_p[(pb + 1) * NU + 32 + lane]);
    }

    // per-lane register state; rp maintained by exact recurrence rp_new = (1-alpha)*rp
    float rs0[5], rs1[5], rl0[5], rl1[5], rp0[5], rp1[5], rd0[5], rd1[5], rv0[5], rv1[5];
#pragma unroll
    for (int t = 0; t < 5; t++) {
        int j = lane + 32 * t;
        rs0[t] = rs1[t] = rl0[t] = rl1[t] = 1.f;
        float rpi = (j < NINEQ) ? (1.0f - sh_[j]) : 0.f;   // rp(0) = G*0 + s0 - h = 1 - h
        rp0[t] = rpi; rp1[t] = rpi;
    }
    float mu0 = 1.0f, mu1 = 1.0f;

    // H 4x4 block-pair assignment (25 pairs + 5 singles, lanes 30,31 idle)
    int bi = 0, bkA = 0, bkB = 0;
    bool hasB = false, active = false;
    {
        int idx = 0;
        for (int r = 0; r < 10; r++) {
            int np = (r + 1) / 2;
            for (int q = 0; q < np; q++) {
                if (idx == lane) { bi = r; bkA = 2 * q; bkB = 2 * q + 1; hasB = true; active = true; }
                idx++;
            }
        }
        for (int r = 0; r < 10; r += 2) {
            if (idx == lane) { bi = r; bkA = r; bkB = r; hasB = false; active = true; }
            idx++;
        }
    }
    bool diagA = (bkA == bi);
    bool diagB = (bkB == bi);

    __syncwarp();

    for (int it = 0; it < IPM_ITERS; it++) {
        // ---- S0: d, v (rp already up to date via recurrence) ----
#pragma unroll
        for (int t = 0; t < 5; t++) {
            int j = lane + 32 * t;
            if (j < NINEQ) {
                float ri0 = __fdividef(1.0f, rs0[t]);
                float ri1 = __fdividef(1.0f, rs1[t]);
                float d0 = rl0[t] * ri0, d1 = rl1[t] * ri1;
                rd0[t] = d0; rd1[t] = d1;
                pD2[j] = pk2(d0, d1);
                float v0 = SIGMA * mu0 * ri0 + d0 * rp0[t];
                float v1 = SIGMA * mu1 * ri1 + d1 * rp1[t];
                rv0[t] = v0; rv1[t] = v1;
                pV2[j] = pk2(v0, v1);
            }
        }
        __syncwarp();

        // ---- S1: H = Q + diag(d) + B^T diag(d) B  (paired dense loop) ----
        {
            u64 acc0[4][4], acc1[4][4];
#pragma unroll
            for (int a = 0; a < 4; a++) {
                float4 v0 = *(const float4*)(sQ + (4 * bi + a) * 44 + 4 * bkA);
                acc0[a][0] = rep2(v0.x); acc0[a][1] = rep2(v0.y);
                acc0[a][2] = rep2(v0.z); acc0[a][3] = rep2(v0.w);
                float4 v1 = *(const float4*)(sQ + (4 * bi + a) * 44 + 4 * bkB);
                acc1[a][0] = rep2(v1.x); acc1[a][1] = rep2(v1.y);
                acc1[a][2] = rep2(v1.z); acc1[a][3] = rep2(v1.w);
            }
            if (diagA) {
#pragma unroll
                for (int a = 0; a < 4; a++) acc0[a][a] = add2(acc0[a][a], pD2[4 * bi + a]);
            }
            if (diagB) {
#pragma unroll
                for (int a = 0; a < 4; a++) acc1[a][a] = add2(acc1[a][a], pD2[4 * bi + a]);
            }
#pragma unroll 2
            for (int j = 0; j < NB; j++) {
                u64 dp = pD2[NU + j];
                const float* br = sB + j * 44;
                float4 gav = *(const float4*)(br + 4 * bi);
                float4 g0  = *(const float4*)(br + 4 * bkA);
                float4 g1  = *(const float4*)(br + 4 * bkB);
                u64 sa[4];
                sa[0] = mul2(dp, rep2(gav.x)); sa[1] = mul2(dp, rep2(gav.y));
                sa[2] = mul2(dp, rep2(gav.z)); sa[3] = mul2(dp, rep2(gav.w));
                u64 rb0[4] = {rep2(g0.x), rep2(g0.y), rep2(g0.z), rep2(g0.w)};
                u64 rb1[4] = {rep2(g1.x), rep2(g1.y), rep2(g1.z), rep2(g1.w)};
#pragma unroll
                for (int a = 0; a < 4; a++)
#pragma unroll
                    for (int c = 0; c < 4; c++) {
                        acc0[a][c] = fma2(sa[a], rb0[c], acc0[a][c]);
                        acc1[a][c] = fma2(sa[a], rb1[c], acc1[a][c]);
                    }
            }
            if (active) {
#pragma unroll
                for (int a = 0; a < 4; a++) {
                    int ob = toff(4 * bi + a);
#pragma unroll
                    for (int c = 0; c < 4; c++)
                        if (!diagA || c <= a) pH2[ob + 4 * bkA + c] = acc0[a][c];
                    if (hasB) {
#pragma unroll
                        for (int c = 0; c < 4; c++)
                            if (!diagB || c <= a) pH2[ob + 4 * bkB + c] = acc1[a][c];
                    }
                }
            }
        }

        // ---- rhs = -(Qu + p + v[:40] + B^T v[40:]) ----
        {
            u64 A0 = add2(pP2[lane], pV2[lane]);
            u64 A1 = (lane < 8) ? add2(pP2[32 + lane], pV2[32 + lane]) : 0ULL;
            const float4* q0 = (const float4*)(sQ + lane * 44);
            const float4* q1 = (const float4*)(sQ + (32 + lane) * 44);
#pragma unroll
            for (int q = 0; q < 10; q++) {
                float4 qv0 = q0[q];
                A0 = fma2(rep2(qv0.x), pU2[4 * q + 0], A0);
                A0 = fma2(rep2(qv0.y), pU2[4 * q + 1], A0);
                A0 = fma2(rep2(qv0.z), pU2[4 * q + 2], A0);
                A0 = fma2(rep2(qv0.w), pU2[4 * q + 3], A0);
                if (lane < 8) {
                    float4 qv1 = q1[q];
                    A1 = fma2(rep2(qv1.x), pU2[4 * q + 0], A1);
                    A1 = fma2(rep2(qv1.y), pU2[4 * q + 1], A1);
                    A1 = fma2(rep2(qv1.z), pU2[4 * q + 2], A1);
                    A1 = fma2(rep2(qv1.w), pU2[4 * q + 3], A1);
                }
            }
#pragma unroll 2
            for (int j = 0; j < NB; j++) {
                const float* br = sB + j * 44;
                A0 = fma2(rep2(br[lane]), pV2[NU + j], A0);
            }
            // cols 32-35 nonzero only for j >= 96; cols 36-39 are zero rows in B
            if (lane < 8) {
#pragma unroll
                for (int j = 96; j < NB; j++) {
                    const float* br = sB + j * 44;
                    A1 = fma2(rep2(br[32 + lane]), pV2[NU + j], A1);
                }
            }
            pR2[lane] = neg2(A0);
            if (lane < 8) pR2[32 + lane] = neg2(A1);
        }
        __syncwarp();

        // ---- S3: blocked Cholesky (panel=8), packed; 1 syncwarp per k ----
        for (int pp = 0; pp < 5; pp++) {
            int k0 = 8 * pp;
            for (int kk = 0; kk < 8; kk++) {
                int k = k0 + kk;
                int ok = toff(k);
                float h0, h1;
                upk2(pH2[ok + k], h0, h1);
                float i0 = rsqrtf(h0);
                float i1 = rsqrtf(h1);
                u64 ip = pk2(i0, i1);
                if (lane == 0) pLi2[k] = ip;
                int r0 = k + 1 + lane, r1 = r0 + 32;
                int or0 = toff(r0), or1 = toff(r1);
                u64 v0 = 0ULL, v1 = 0ULL;
                if (r0 < NU) { v0 = mul2(pH2[or0 + k], ip); pH2[or0 + k] = v0; }
                if (r1 < NU) { v1 = mul2(pH2[or1 + k], ip); pH2[or1 + k] = v1; }
                for (int j = k + 1; j < k0 + 8; j++) {
                    u64 m = __shfl_sync(0xffffffffu, v0, j - k - 1);
                    u64 nm = neg2(m);
                    if (r0 < NU && r0 >= j) pH2[or0 + j] = fma2(nm, v0, pH2[or0 + j]);
                    if (r1 < NU)            pH2[or1 + j] = fma2(nm, v1, pH2[or1 + j]);
                }
                __syncwarp();
            }
            if (pp < 4) {
                int base = k0 + 8;
                int nbk = (NU - base) >> 2;
                int cnt = nbk * (nbk + 1) / 2;
                for (int bb = lane; bb < cnt; bb += 32) {
                    int t = bb, r = 0;
                    while (t > r) { t -= r + 1; r++; }
                    int c = t;
                    int ri = base + 4 * r, ci = base + 4 * c;
                    bool diag = (r == c);
                    int oR[4], oC[4];
                    oR[0] = toff(ri);
                    oR[1] = oR[0] + ri + 1; oR[2] = oR[1] + ri + 2; oR[3] = oR[2] + ri + 3;
                    oC[0] = toff(ci);
                    oC[1] = oC[0] + ci + 1; oC[2] = oC[1] + ci + 2; oC[3] = oC[2] + ci + 3;
                    u64 a2[4][4];
#pragma unroll
                    for (int a = 0; a < 4; a++)
#pragma unroll
                        for (int cb = 0; cb < 4; cb++)
                            a2[a][cb] = pH2[oR[a] + ci + cb];
#pragma unroll
                    for (int kk = 0; kk < 8; kk++) {
                        u64 nla[4], lb[4];
#pragma unroll
                        for (int a = 0; a < 4; a++) nla[a] = neg2(pH2[oR[a] + k0 + kk]);
#pragma unroll
                        for (int cb = 0; cb < 4; cb++) lb[cb] = pH2[oC[cb] + k0 + kk];
#pragma unroll
                        for (int a = 0; a < 4; a++)
#pragma unroll
                            for (int cb = 0; cb < 4; cb++)
                                a2[a][cb] = fma2(nla[a], lb[cb], a2[a][cb]);
                    }
#pragma unroll
                    for (int a = 0; a < 4; a++)
#pragma unroll
                        for (int cb = 0; cb < 4; cb++)
                            if (!diag || cb <= a) pH2[oR[a] + ci + cb] = a2[a][cb];
                }
                __syncwarp();
            }
        }

        // ---- triangular solves (packed, fully unrolled) ----
        {
            int offL0 = toff(lane);
            int offL1 = toff(32 + lane);
            u64 a0 = pR2[lane];
            u64 a1 = (lane < 8) ? pR2[32 + lane] : 0ULL;
#pragma unroll
            for (int k = 0; k < NU; k++) {
                u64 src = (k < 32) ? a0 : a1;
                u64 y = mul2(__shfl_sync(0xffffffffu, src, k & 31), pLi2[k]);
                if (k < 32) { if (lane == k) a0 = y; }
                else        { if (lane == k - 32) a1 = y; }
                u64 ny = neg2(y);
                if (lane > k) a0 = fma2(pH2[offL0 + k], ny, a0);
                if (lane < 8 && 32 + lane > k) a1 = fma2(pH2[offL1 + k], ny, a1);
            }
#pragma unroll
            for (int k = NU - 1; k >= 0; k--) {
                const int offk = toff(k);
                u64 src = (k < 32) ? a0 : a1;
                u64 x = mul2(__shfl_sync(0xffffffffu, src, k & 31), pLi2[k]);
                if (k < 32) { if (lane == k) a0 = x; }
                else        { if (lane == k - 32) a1 = x; }
                u64 nx = neg2(x);
                if (lane < k) a0 = fma2(pH2[offk + lane], nx, a0);
                if (lane < 8 && 32 + lane < k) a1 = fma2(pH2[offk + 32 + lane], nx, a1);
            }
            pDU2[lane] = a0;
            if (lane < 8) pDU2[32 + lane] = a1;
        }
        __syncwarp();

        // ---- S4: ds, dlam, alpha (sparse bounds + fast div; regs for d,v,rp) ----
        float am0 = BIGF, am1 = BIGF;
        float ds0a[5], ds1a[5];
#pragma unroll
        for (int t = 0; t < 5; t++) {
            int j = lane + 32 * t;
            if (j < NINEQ) {
                u64 g;
                if (j < NU) g = pDU2[j];
                else {
                    const float4* br4 = (const float4*)(sB + (j - NU) * 44);
                    u64 acc = 0ULL;
                    const int bnd = (t == 1) ? 2 : (t == 2) ? 5 : (t == 3) ? 8 : 9;
#pragma unroll
                    for (int q = 0; q < bnd; q++) {
                        float4 bv = br4[q];
                        acc = fma2(rep2(bv.x), pDU2[4 * q + 0], acc);
                        acc = fma2(rep2(bv.y), pDU2[4 * q + 1], acc);
                        acc = fma2(rep2(bv.z), pDU2[4 * q + 2], acc);
                        acc = fma2(rep2(bv.w), pDU2[4 * q + 3], acc);
                    }
                    g = acc;
                }
                float g0, g1;
                upk2(g, g0, g1);
                float ds0 = -rp0[t] - g0, ds1 = -rp1[t] - g1;
                float dl0 = rv0[t] - rl0[t] + rd0[t] * g0;
                float dl1 = rv1[t] - rl1[t] + rd1[t] * g1;
                ds0a[t] = ds0; ds1a[t] = ds1;
                rv0[t] = dl0; rv1[t] = dl1;          // alias: v regs now hold dlam
                float q0 = (ds0 < 0.f) ? __fdividef(-rs0[t], ds0) : BIGF;
                float q1 = (dl0 < 0.f) ? __fdividef(-rl0[t], dl0) : BIGF;
                am0 = fminf(am0, fminf(q0, q1));
                float q2 = (ds1 < 0.f) ? __fdividef(-rs1[t], ds1) : BIGF;
                float q3 = (dl1 < 0.f) ? __fdividef(-rl1[t], dl1) : BIGF;
                am1 = fminf(am1, fminf(q2, q3));
            }
        }
#pragma unroll
        for (int o = 16; o; o >>= 1) {
            am0 = fminf(am0, __shfl_xor_sync(0xffffffffu, am0, o));
            am1 = fminf(am1, __shfl_xor_sync(0xffffffffu, am1, o));
        }
        float al0 = fminf(1.0f, 0.99f * am0);
        float al1 = fminf(1.0f, 0.99f * am1);

        // ---- S5: update + mu + rp recurrence ----
        float ls0 = 0.f, ls1 = 0.f;
        float om0 = 1.0f - al0, om1 = 1.0f - al1;
#pragma unroll
        for (int t = 0; t < 5; t++) {
            int j = lane + 32 * t;
            if (j < NINEQ) {
                rs0[t] += al0 * ds0a[t];  rl0[t] += al0 * rv0[t];  ls0 += rs0[t] * rl0[t];
                rs1[t] += al1 * ds1a[t];  rl1[t] += al1 * rv1[t];  ls1 += rs1[t] * rl1[t];
                rp0[t] *= om0;  rp1[t] *= om1;       // exact: rp_new = (1-alpha) rp
            }
        }
#pragma unroll
        for (int o = 16; o; o >>= 1) {
            ls0 += __shfl_xor_sync(0xffffffffu, ls0, o);
            ls1 += __shfl_xor_sync(0xffffffffu, ls1, o);
        }
        mu0 = ls0 * (1.0f / 148.0f);
        mu1 = ls1 * (1.0f / 148.0f);

        u64 alp = pk2(al0, al1);
        pU2[lane] = fma2(alp, pDU2[lane], pU2[lane]);
        if (lane < 8) pU2[32 + lane] = fma2(alp, pDU2[32 + lane], pU2[32 + lane]);
        __syncwarp();
    }

    // ---- output: Q_value = 0.5 u'Qu + p'u ; u0 ----
    {
        const float4* q0 = (const float4*)(sQ + lane * 44);
        const float4* q1 = (const float4*)(sQ + (32 + lane) * 44);
        u64 qu0 = 0ULL, qu1 = 0ULL;
#pragma unroll
        for (int q = 0; q < 10; q++) {
            float4 qv0 = q0[q];
            qu0 = fma2(rep2(qv0.x), pU2[4 * q + 0], qu0);
            qu0 = fma2(rep2(qv0.y), pU2[4 * q + 1], qu0);
            qu0 = fma2(rep2(qv0.z), pU2[4 * q + 2], qu0);
            qu0 = fma2(rep2(qv0.w), pU2[4 * q + 3], qu0);
            if (lane < 8) {
                float4 qv1 = q1[q];
                qu1 = fma2(rep2(qv1.x), pU2[4 * q + 0], qu1);
                qu1 = fma2(rep2(qv1.y), pU2[4 * q + 1], qu1);
                qu1 = fma2(rep2(qv1.z), pU2[4 * q + 2], qu1);
                qu1 = fma2(rep2(qv1.w), pU2[4 * q + 3], qu1);
            }
        }
        float qa0, qa1, ua0, ua1, pa0, pa1;
        upk2(qu0, qa0, qa1);
        upk2(pU2[lane], ua0, ua1);
        upk2(pP2[lane], pa0, pa1);
        float part0 = ua0 * (0.5f * qa0 + pa0);
        float part1 = ua1 * (0.5f * qa1 + pa1);
        if (lane < 8) {
            float qb0, qb1, ub0, ub1, pb0, pb1;
            upk2(qu1, qb0, qb1);
            upk2(pU2[32 + lane], ub0, ub1);
            upk2(pP2[32 + lane], pb0, pb1);
            part0 += ub0 * (0.5f * qb0 + pb0);
            part1 += ub1 * (0.5f * qb1 + pb1);
        }
#pragma unroll
        for (int o = 16; o; o >>= 1) {
            part0 += __shfl_xor_sync(0xffffffffu, part0, o);
            part1 += __shfl_xor_sync(0xffffffffu, part1, o);
        }
        if (lane == 0) {
            float u00, u01;
            upk2(pU2[0], u00, u01);
            out[pb] = part0;
            out[pb + 1] = part1;
            out[BATCH + pb] = u00;
            out[BATCH + pb + 1] = u01;
        }
    }
}

// ================= launch =================
extern "C" void kernel_launch(void* const* d_in, const int* in_sizes, int n_in,
                              void* d_out, int out_size) {
    const float* x  = (const float*)d_in[0];
    const float* W1 = (const float*)d_in[1];
    const float* b1 = (const float*)d_in[2];
    const float* W2 = (const float*)d_in[3];
    const float* b2 = (const float*)d_in[4];
    const float* L  = (const float*)d_in[5];
    const float* LP = (const float*)d_in[6];
    const float* LR = (const float*)d_in[7];
    const float* A  = (const float*)d_in[8];
    const float* Bm = (const float*)d_in[9];
    const float* u0 = (const float*)d_in[10];
    const float* s0 = (const float*)d_in[11];

    cudaFuncSetAttribute(ipm_kernel, cudaFuncAttributeMaxDynamicSharedMemorySize, SMEM_BYTES);

    setup_kernel<<<1, 128>>>(L, LP, LR, A, Bm, u0, s0);
    mlp_kernel<<<BATCH / 4, 128>>>(x, W1, b1, W2, b2);
    ipm_kernel<<<BATCH / PPC, NTH, SMEM_BYTES>>>((float*)d_out);
}

// round 13
// speedup vs baseline: 1.0192x; 1.0192x over previous
#include <cuda_runtime.h>
#include <math.h>

#define NIN   12
#define NOUT  4
#define NHID  512
#define NU    40
#define NB    108
#define NINEQ 148
#define BATCH 4096
#define IPM_ITERS 20
#define SIGMA 0.1f
#define BIGF  1000000000.0f
#define EPSF  0.0001f

#define WPB   8
#define PPW   2
#define PPC   (WPB * PPW)
#define NTH   (32 * WPB)

// shared scalar layout (floats)
#define SQ_OFF 0                // 40*44 = 1760
#define SB_OFF 1760             // 108*44 = 4752
#define SH_OFF 6512             // 148 -> pad to 6672
#define PR_OFF 6672

// per-pair packed layout (u64 units)
#define H2_OFF   0              // 820 packed lower triangle
#define D2_OFF   820            // 148
#define V2_OFF   968            // 148
#define U2_OFF   1116           // 40
#define RHS2_OFF 1156           // 40
#define DU2_OFF  1196           // 40
#define LDI2_OFF 1236           // 40
#define P2_OFF   1276           // 40
#define PSTRIDE_U64 1320

#define SMEM_FLOATS (PR_OFF + WPB * PSTRIDE_U64 * 2)
#define SMEM_BYTES  (SMEM_FLOATS * 4)

typedef unsigned long long u64;

__device__ __forceinline__ u64 pk2(float lo, float hi) {
    u64 r; asm("mov.b64 %0,{%1,%2};" : "=l"(r) : "f"(lo), "f"(hi)); return r;
}
__device__ __forceinline__ void upk2(u64 v, float& lo, float& hi) {
    asm("mov.b64 {%0,%1},%2;" : "=f"(lo), "=f"(hi) : "l"(v));
}
__device__ __forceinline__ u64 rep2(float x) { return pk2(x, x); }
__device__ __forceinline__ u64 fma2(u64 a, u64 b, u64 c) {
    u64 d; asm("fma.rn.f32x2 %0,%1,%2,%3;" : "=l"(d) : "l"(a), "l"(b), "l"(c)); return d;
}
__device__ __forceinline__ u64 mul2(u64 a, u64 b) {
    u64 d; asm("mul.rn.f32x2 %0,%1,%2;" : "=l"(d) : "l"(a), "l"(b)); return d;
}
__device__ __forceinline__ u64 add2(u64 a, u64 b) {
    u64 d; asm("add.rn.f32x2 %0,%1,%2;" : "=l"(d) : "l"(a), "l"(b)); return d;
}
__device__ __forceinline__ u64 neg2(u64 a) { return a ^ 0x8000000080000000ULL; }

__device__ float g_Q[NU * NU];
__device__ float g_B[NB * NU];
__device__ float g_h[NINEQ];
__device__ float g_p[BATCH * NU];

__device__ __forceinline__ float lrelu(float x) { return x > 0.f ? x : 0.01f * x; }
__device__ __forceinline__ int toff(int r) { return (r * (r + 1)) >> 1; }

// ================= setup =================
__global__ void setup_kernel(const float* __restrict__ L, const float* __restrict__ LP,
                             const float* __restrict__ LR, const float* __restrict__ A,
                             const float* __restrict__ Bm, const float* __restrict__ u0,
                             const float* __restrict__ s0) {
    __shared__ float sQx[144], sP[144], sR[16], sBp[9 * 48];
    __shared__ float sBh[NB * NU];
    __shared__ float sM[NB * NU];
    int tid = threadIdx.x;
    const int NTs = 128;

    for (int idx = tid; idx < 144; idx += NTs) {
        int i = idx / 12, j = idx % 12;
        int mn = i < j ? i : j;
        float a = 0.f, b = 0.f;
        for (int k = 0; k <= mn; k++) {
            a += L[i * 12 + k] * L[j * 12 + k];
            b += LP[i * 12 + k] * LP[j * 12 + k];
        }
        sQx[idx] = a + (i == j ? EPSF : 0.f);
        sP[idx]  = b + (i == j ? EPSF : 0.f);
    }
    for (int idx = tid; idx < 16; idx += NTs) {
        int i = idx / 4, j = idx % 4;
        int mn = i < j ? i : j;
        float a = 0.f;
        for (int k = 0; k <= mn; k++) a += LR[i * 4 + k] * LR[j * 4 + k];
        sR[idx] = a + (i == j ? EPSF : 0.f);
    }
    if (tid < 48) sBp[tid] = Bm[tid];
    __syncthreads();

    for (int m = 1; m < 9; m++) {
        if (tid < 48) {
            int i = tid / 4, o = tid % 4;
            float v = 0.f;
            for (int k = 0; k < 12; k++) v += A[i * 12 + k] * sBp[(m - 1) * 48 + k * 4 + o];
            sBp[m * 48 + tid] = v;
        }
        __syncthreads();
    }

    for (int idx = tid; idx < NB * NU; idx += NTs) {
        int row = idx / NU, col = idx % NU;
        int rb = row / 12, i = row % 12, cb = col / 4, o = col % 4;
        float v = (cb <= rb) ? sBp[(rb - cb) * 48 + i * 4 + o] : 0.f;
        sBh[idx] = v;
        g_B[idx] = v;
    }
    __syncthreads();

    for (int idx = tid; idx < NB * NU; idx += NTs) {
        int row = idx / NU, col = idx % NU;
        int rb = row / 12, i = row % 12;
        const float* Qd = (rb < 8) ? sQx : sP;
        float a = 0.f;
        for (int k = 0; k < 12; k++) a += Qd[i * 12 + k] * sBh[(rb * 12 + k) * NU + col];
        sM[idx] = a;
    }
    __syncthreads();

    for (int idx = tid; idx < NU * NU; idx += NTs) {
        int a_ = idx / NU, b_ = idx % NU;
        float v = (a_ / 4 == b_ / 4) ? sR[(a_ % 4) * 4 + (b_ % 4)] : 0.f;
        for (int r = 0; r < NB; r++) v += sBh[r * NU + a_] * sM[r * NU + b_];
        g_Q[idx] = v;
    }

    for (int j = tid; j < NINEQ; j += NTs) {
        float v = s0[j];
        if (j < NU) v += u0[j];
        else {
            for (int i = 0; i < NU; i++) v += sBh[(j - NU) * NU + i] * u0[i];
        }
        g_h[j] = v;
    }
}

// ================= MLP =================
__global__ void mlp_kernel(const float* __restrict__ x, const float* __restrict__ W1,
                           const float* __restrict__ b1, const float* __restrict__ W2,
                           const float* __restrict__ b2) {
    __shared__ float hbuf[4][NHID];
    int warp = threadIdx.x >> 5, lane = threadIdx.x & 31;
    int row = blockIdx.x * 4 + warp;

    float xr[NIN];
#pragma unroll
    for (int c = 0; c < NIN; c++) xr[c] = x[row * NIN + c];

#pragma unroll
    for (int t = 0; t < NHID / 32; t++) {
        int j = lane + 32 * t;
        const float* w = W1 + j * NIN;
        float acc = b1[j];
#pragma unroll
        for (int c = 0; c < NIN; c++) acc += w[c] * xr[c];
        hbuf[warp][j] = lrelu(acc);
    }
    __syncwarp();

    for (int k = 0; k < NU; k++) {
        const float* w = W2 + k * NHID;
        float acc = 0.f;
#pragma unroll
        for (int t = 0; t < NHID / 32; t++) {
            int j = lane + 32 * t;
            acc += w[j] * hbuf[warp][j];
        }
#pragma unroll
        for (int o = 16; o; o >>= 1) acc += __shfl_xor_sync(0xffffffffu, acc, o);
        if (lane == 0) g_p[row * NU + k] = lrelu(acc + b2[k]);
    }
}

// ================= IPM: two problems per warp, f32x2, rp recurrence =================
__global__ void __launch_bounds__(NTH, 2) ipm_kernel(float* __restrict__ out) {
    extern __shared__ float sm[];
    float* sQ  = sm + SQ_OFF;    // stride 44
    float* sB  = sm + SB_OFF;    // stride 44
    float* sh_ = sm + SH_OFF;

    int tid = threadIdx.x;
    int lane = tid & 31, wid = tid >> 5;

    for (int idx = tid; idx < NU * NU; idx += NTH) sQ[(idx / NU) * 44 + idx % NU] = g_Q[idx];
    for (int idx = tid; idx < NB * NU; idx += NTH) sB[(idx / NU) * 44 + idx % NU] = g_B[idx];
    for (int idx = tid; idx < NINEQ; idx += NTH) sh_[idx] = g_h[idx];
    __syncthreads();

    int pb = blockIdx.x * PPC + wid * PPW;
    u64* PR = (u64*)(sm + PR_OFF) + wid * PSTRIDE_U64;
    u64* pH2  = PR + H2_OFF;
    u64* pD2  = PR + D2_OFF;
    u64* pV2  = PR + V2_OFF;
    u64* pU2  = PR + U2_OFF;
    u64* pR2  = PR + RHS2_OFF;
    u64* pDU2 = PR + DU2_OFF;
    u64* pLi2 = PR + LDI2_OFF;
    u64* pP2  = PR + P2_OFF;

    if (lane < NU) {
        pU2[lane] = 0ULL;
        pP2[lane] = pk2(g_p[pb * NU + lane], g_p[(pb + 1) * NU + lane]);
    }
    if (lane < 8) {
        pU2[32 + lane] = 0ULL;
        pP2[32 + lane] = pk2(g_p[pb * NU + 32 + lane], g_p[(pb + 1) * NU + 32 + lane]);
    }

    // per-lane scalar state; rp via exact recurrence rp_new = (1-alpha) * rp
    float rs0[5], rs1[5], rl0[5], rl1[5], rp0[5], rp1[5];
#pragma unroll
    for (int t = 0; t < 5; t++) {
        int j = lane + 32 * t;
        rs0[t] = rs1[t] = rl0[t] = rl1[t] = 1.f;
        float rpi = (j < NINEQ) ? (1.0f - sh_[j]) : 0.f;   // rp(0) = G*0 + s0 - h = 1 - h
        rp0[t] = rpi; rp1[t] = rpi;
    }
    float mu0 = 1.0f, mu1 = 1.0f;

    // H 4x4 block-pair assignment (25 pairs + 5 singles, lanes 30,31 idle)
    int bi = 0, bkA = 0, bkB = 0;
    bool hasB = false, active = false;
    {
        int idx = 0;
        for (int r = 0; r < 10; r++) {
            int np = (r + 1) / 2;
            for (int q = 0; q < np; q++) {
                if (idx == lane) { bi = r; bkA = 2 * q; bkB = 2 * q + 1; hasB = true; active = true; }
                idx++;
            }
        }
        for (int r = 0; r < 10; r += 2) {
            if (idx == lane) { bi = r; bkA = r; bkB = r; hasB = false; active = true; }
            idx++;
        }
    }
    bool diagA = (bkA == bi);
    bool diagB = (bkB == bi);

    __syncwarp();

    for (int it = 0; it < IPM_ITERS; it++) {
        // ---- S0: d, v from register rp (no B@u dot needed) ----
#pragma unroll
        for (int t = 0; t < 5; t++) {
            int j = lane + 32 * t;
            if (j < NINEQ) {
                float ri0 = __fdividef(1.0f, rs0[t]);
                float ri1 = __fdividef(1.0f, rs1[t]);
                float d0 = rl0[t] * ri0, d1 = rl1[t] * ri1;
                pD2[j] = pk2(d0, d1);
                float v0 = SIGMA * mu0 * ri0 + d0 * rp0[t];
                float v1 = SIGMA * mu1 * ri1 + d1 * rp1[t];
                pV2[j] = pk2(v0, v1);
            }
        }
        __syncwarp();

        // ---- S1: H = Q + diag(d) + B^T diag(d) B  (paired dense loop) ----
        {
            u64 acc0[4][4], acc1[4][4];
#pragma unroll
            for (int a = 0; a < 4; a++) {
                float4 v0 = *(const float4*)(sQ + (4 * bi + a) * 44 + 4 * bkA);
                acc0[a][0] = rep2(v0.x); acc0[a][1] = rep2(v0.y);
                acc0[a][2] = rep2(v0.z); acc0[a][3] = rep2(v0.w);
                float4 v1 = *(const float4*)(sQ + (4 * bi + a) * 44 + 4 * bkB);
                acc1[a][0] = rep2(v1.x); acc1[a][1] = rep2(v1.y);
                acc1[a][2] = rep2(v1.z); acc1[a][3] = rep2(v1.w);
            }
            if (diagA) {
#pragma unroll
                for (int a = 0; a < 4; a++) acc0[a][a] = add2(acc0[a][a], pD2[4 * bi + a]);
            }
            if (diagB) {
#pragma unroll
                for (int a = 0; a < 4; a++) acc1[a][a] = add2(acc1[a][a], pD2[4 * bi + a]);
            }
#pragma unroll 2
            for (int j = 0; j < NB; j++) {
                u64 dp = pD2[NU + j];
                const float* br = sB + j * 44;
                float4 gav = *(const float4*)(br + 4 * bi);
                float4 g0  = *(const float4*)(br + 4 * bkA);
                float4 g1  = *(const float4*)(br + 4 * bkB);
                u64 sa[4];
                sa[0] = mul2(dp, rep2(gav.x)); sa[1] = mul2(dp, rep2(gav.y));
                sa[2] = mul2(dp, rep2(gav.z)); sa[3] = mul2(dp, rep2(gav.w));
                u64 rb0[4] = {rep2(g0.x), rep2(g0.y), rep2(g0.z), rep2(g0.w)};
                u64 rb1[4] = {rep2(g1.x), rep2(g1.y), rep2(g1.z), rep2(g1.w)};
#pragma unroll
                for (int a = 0; a < 4; a++)
#pragma unroll
                    for (int c = 0; c < 4; c++) {
                        acc0[a][c] = fma2(sa[a], rb0[c], acc0[a][c]);
                        acc1[a][c] = fma2(sa[a], rb1[c], acc1[a][c]);
                    }
            }
            if (active) {
#pragma unroll
                for (int a = 0; a < 4; a++) {
                    int ob = toff(4 * bi + a);
#pragma unroll
                    for (int c = 0; c < 4; c++)
                        if (!diagA || c <= a) pH2[ob + 4 * bkA + c] = acc0[a][c];
                    if (hasB) {
#pragma unroll
                        for (int c = 0; c < 4; c++)
                            if (!diagB || c <= a) pH2[ob + 4 * bkB + c] = acc1[a][c];
                    }
                }
            }
        }

        // ---- rhs = -(Qu + p + v[:40] + B^T v[40:]) ----
        {
            u64 A0 = add2(pP2[lane], pV2[lane]);
            u64 A1 = (lane < 8) ? add2(pP2[32 + lane], pV2[32 + lane]) : 0ULL;
            const float4* q0 = (const float4*)(sQ + lane * 44);
            const float4* q1 = (const float4*)(sQ + (32 + lane) * 44);
#pragma unroll
            for (int q = 0; q < 10; q++) {
                float4 qv0 = q0[q];
                A0 = fma2(rep2(qv0.x), pU2[4 * q + 0], A0);
                A0 = fma2(rep2(qv0.y), pU2[4 * q + 1], A0);
                A0 = fma2(rep2(qv0.z), pU2[4 * q + 2], A0);
                A0 = fma2(rep2(qv0.w), pU2[4 * q + 3], A0);
                if (lane < 8) {
                    float4 qv1 = q1[q];
                    A1 = fma2(rep2(qv1.x), pU2[4 * q + 0], A1);
                    A1 = fma2(rep2(qv1.y), pU2[4 * q + 1], A1);
                    A1 = fma2(rep2(qv1.z), pU2[4 * q + 2], A1);
                    A1 = fma2(rep2(qv1.w), pU2[4 * q + 3], A1);
                }
            }
#pragma unroll 2
            for (int j = 0; j < NB; j++) {
                const float* br = sB + j * 44;
                A0 = fma2(rep2(br[lane]), pV2[NU + j], A0);
            }
            // cols 32-35 nonzero only for j >= 96; cols 36-39 are zero rows in B
            if (lane < 8) {
#pragma unroll
                for (int j = 96; j < NB; j++) {
                    const float* br = sB + j * 44;
                    A1 = fma2(rep2(br[32 + lane]), pV2[NU + j], A1);
                }
            }
            pR2[lane] = neg2(A0);
            if (lane < 8) pR2[32 + lane] = neg2(A1);
        }
        __syncwarp();

        // ---- S3: blocked Cholesky (panel=8), packed; 1 syncwarp per k ----
        for (int pp = 0; pp < 5; pp++) {
            int k0 = 8 * pp;
            for (int kk = 0; kk < 8; kk++) {
                int k = k0 + kk;
                int ok = toff(k);
                float h0, h1;
                upk2(pH2[ok + k], h0, h1);
                float i0 = rsqrtf(h0);
                float i1 = rsqrtf(h1);
                u64 ip = pk2(i0, i1);
                if (lane == 0) pLi2[k] = ip;
                int r0 = k + 1 + lane, r1 = r0 + 32;
                int or0 = toff(r0), or1 = toff(r1);
                u64 v0 = 0ULL, v1 = 0ULL;
                if (r0 < NU) { v0 = mul2(pH2[or0 + k], ip); pH2[or0 + k] = v0; }
                if (r1 < NU) { v1 = mul2(pH2[or1 + k], ip); pH2[or1 + k] = v1; }
                for (int j = k + 1; j < k0 + 8; j++) {
                    u64 m = __shfl_sync(0xffffffffu, v0, j - k - 1);
                    u64 nm = neg2(m);
                    if (r0 < NU && r0 >= j) pH2[or0 + j] = fma2(nm, v0, pH2[or0 + j]);
                    if (r1 < NU)            pH2[or1 + j] = fma2(nm, v1, pH2[or1 + j]);
                }
                __syncwarp();
            }
            if (pp < 4) {
                int base = k0 + 8;
                int nbk = (NU - base) >> 2;
                int cnt = nbk * (nbk + 1) / 2;
                for (int bb = lane; bb < cnt; bb += 32) {
                    int t = bb, r = 0;
                    while (t > r) { t -= r + 1; r++; }
                    int c = t;
                    int ri = base + 4 * r, ci = base + 4 * c;
                    bool diag = (r == c);
                    int oR[4], oC[4];
                    oR[0] = toff(ri);
                    oR[1] = oR[0] + ri + 1; oR[2] = oR[1] + ri + 2; oR[3] = oR[2] + ri + 3;
                    oC[0] = toff(ci);
                    oC[1] = oC[0] + ci + 1; oC[2] = oC[1] + ci + 2; oC[3] = oC[2] + ci + 3;
                    u64 a2[4][4];
#pragma unroll
                    for (int a = 0; a < 4; a++)
#pragma unroll
                        for (int cb = 0; cb < 4; cb++)
                            a2[a][cb] = pH2[oR[a] + ci + cb];
#pragma unroll
                    for (int kk = 0; kk < 8; kk++) {
                        u64 nla[4], lb[4];
#pragma unroll
                        for (int a = 0; a < 4; a++) nla[a] = neg2(pH2[oR[a] + k0 + kk]);
#pragma unroll
                        for (int cb = 0; cb < 4; cb++) lb[cb] = pH2[oC[cb] + k0 + kk];
#pragma unroll
                        for (int a = 0; a < 4; a++)
#pragma unroll
                            for (int cb = 0; cb < 4; cb++)
                                a2[a][cb] = fma2(nla[a], lb[cb], a2[a][cb]);
                    }
#pragma unroll
                    for (int a = 0; a < 4; a++)
#pragma unroll
                        for (int cb = 0; cb < 4; cb++)
                            if (!diag || cb <= a) pH2[oR[a] + ci + cb] = a2[a][cb];
                }
                __syncwarp();
            }
        }

        // ---- triangular solves (packed, fully unrolled) ----
        {
            int offL0 = toff(lane);
            int offL1 = toff(32 + lane);
            u64 a0 = pR2[lane];
            u64 a1 = (lane < 8) ? pR2[32 + lane] : 0ULL;
#pragma unroll
            for (int k = 0; k < NU; k++) {
                u64 src = (k < 32) ? a0 : a1;
                u64 y = mul2(__shfl_sync(0xffffffffu, src, k & 31), pLi2[k]);
                if (k < 32) { if (lane == k) a0 = y; }
                else        { if (lane == k - 32) a1 = y; }
                u64 ny = neg2(y);
                if (lane > k) a0 = fma2(pH2[offL0 + k], ny, a0);
                if (lane < 8 && 32 + lane > k) a1 = fma2(pH2[offL1 + k], ny, a1);
            }
#pragma unroll
            for (int k = NU - 1; k >= 0; k--) {
                const int offk = toff(k);
                u64 src = (k < 32) ? a0 : a1;
                u64 x = mul2(__shfl_sync(0xffffffffu, src, k & 31), pLi2[k]);
                if (k < 32) { if (lane == k) a0 = x; }
                else        { if (lane == k - 32) a1 = x; }
                u64 nx = neg2(x);
                if (lane < k) a0 = fma2(pH2[offk + lane], nx, a0);
                if (lane < 8 && 32 + lane < k) a1 = fma2(pH2[offk + 32 + lane], nx, a1);
            }
            pDU2[lane] = a0;
            if (lane < 8) pDU2[32 + lane] = a1;
        }
        __syncwarp();

        // ---- S4: ds, dlam, alpha (d,v from smem as in R11) ----
        float am0 = BIGF, am1 = BIGF;
        float ds0a[5], ds1a[5], dl0a[5], dl1a[5];
#pragma unroll
        for (int t = 0; t < 5; t++) {
            int j = lane + 32 * t;
            if (j < NINEQ) {
                u64 g;
                if (j < NU) g = pDU2[j];
                else {
                    const float4* br4 = (const float4*)(sB + (j - NU) * 44);
                    u64 acc = 0ULL;
                    const int bnd = (t == 1) ? 2 : (t == 2) ? 5 : (t == 3) ? 8 : 9;
#pragma unroll
                    for (int q = 0; q < bnd; q++) {
                        float4 bv = br4[q];
                        acc = fma2(rep2(bv.x), pDU2[4 * q + 0], acc);
                        acc = fma2(rep2(bv.y), pDU2[4 * q + 1], acc);
                        acc = fma2(rep2(bv.z), pDU2[4 * q + 2], acc);
                        acc = fma2(rep2(bv.w), pDU2[4 * q + 3], acc);
                    }
                    g = acc;
                }
                float g0, g1, d0, d1, v0, v1;
                upk2(g, g0, g1);
                upk2(pD2[j], d0, d1);
                upk2(pV2[j], v0, v1);
                float ds0 = -rp0[t] - g0, ds1 = -rp1[t] - g1;
                float dl0 = v0 - rl0[t] + d0 * g0;
                float dl1 = v1 - rl1[t] + d1 * g1;
                ds0a[t] = ds0; ds1a[t] = ds1; dl0a[t] = dl0; dl1a[t] = dl1;
                float q0 = (ds0 < 0.f) ? __fdividef(-rs0[t], ds0) : BIGF;
                float q1 = (dl0 < 0.f) ? __fdividef(-rl0[t], dl0) : BIGF;
                am0 = fminf(am0, fminf(q0, q1));
                float q2 = (ds1 < 0.f) ? __fdividef(-rs1[t], ds1) : BIGF;
                float q3 = (dl1 < 0.f) ? __fdividef(-rl1[t], dl1) : BIGF;
                am1 = fminf(am1, fminf(q2, q3));
            }
        }
#pragma unroll
        for (int o = 16; o; o >>= 1) {
            am0 = fminf(am0, __shfl_xor_sync(0xffffffffu, am0, o));
            am1 = fminf(am1, __shfl_xor_sync(0xffffffffu, am1, o));
        }
        float al0 = fminf(1.0f, 0.99f * am0);
        float al1 = fminf(1.0f, 0.99f * am1);

        // ---- S5: update + mu + rp recurrence ----
        float ls0 = 0.f, ls1 = 0.f;
        float om0 = 1.0f - al0, om1 = 1.0f - al1;
#pragma unroll
        for (int t = 0; t < 5; t++) {
            int j = lane + 32 * t;
            if (j < NINEQ) {
                rs0[t] += al0 * ds0a[t];  rl0[t] += al0 * dl0a[t];  ls0 += rs0[t] * rl0[t];
                rs1[t] += al1 * ds1a[t];  rl1[t] += al1 * dl1a[t];  ls1 += rs1[t] * rl1[t];
                rp0[t] *= om0;  rp1[t] *= om1;       // exact: rp_new = (1-alpha) rp
            }
        }
#pragma unroll
        for (int o = 16; o; o >>= 1) {
            ls0 += __shfl_xor_sync(0xffffffffu, ls0, o);
            ls1 += __shfl_xor_sync(0xffffffffu, ls1, o);
        }
        mu0 = ls0 * (1.0f / 148.0f);
        mu1 = ls1 * (1.0f / 148.0f);

        u64 alp = pk2(al0, al1);
        pU2[lane] = fma2(alp, pDU2[lane], pU2[lane]);
        if (lane < 8) pU2[32 + lane] = fma2(alp, pDU2[32 + lane], pU2[32 + lane]);
        __syncwarp();
    }

    // ---- output: Q_value = 0.5 u'Qu + p'u ; u0 ----
    {
        const float4* q0 = (const float4*)(sQ + lane * 44);
        const float4* q1 = (const float4*)(sQ + (32 + lane) * 44);
        u64 qu0 = 0ULL, qu1 = 0ULL;
#pragma unroll
        for (int q = 0; q < 10; q++) {
            float4 qv0 = q0[q];
            qu0 = fma2(rep2(qv0.x), pU2[4 * q + 0], qu0);
            qu0 = fma2(rep2(qv0.y), pU2[4 * q + 1], qu0);
            qu0 = fma2(rep2(qv0.z), pU2[4 * q + 2], qu0);
            qu0 = fma2(rep2(qv0.w), pU2[4 * q + 3], qu0);
            if (lane < 8) {
                float4 qv1 = q1[q];
                qu1 = fma2(rep2(qv1.x), pU2[4 * q + 0], qu1);
                qu1 = fma2(rep2(qv1.y), pU2[4 * q + 1], qu1);
                qu1 = fma2(rep2(qv1.z), pU2[4 * q + 2], qu1);
                qu1 = fma2(rep2(qv1.w), pU2[4 * q + 3], qu1);
            }
        }
        float qa0, qa1, ua0, ua1, pa0, pa1;
        upk2(qu0, qa0, qa1);
        upk2(pU2[lane], ua0, ua1);
        upk2(pP2[lane], pa0, pa1);
        float part0 = ua0 * (0.5f * qa0 + pa0);
        float part1 = ua1 * (0.5f * qa1 + pa1);
        if (lane < 8) {
            float qb0, qb1, ub0, ub1, pb0, pb1;
            upk2(qu1, qb0, qb1);
            upk2(pU2[32 + lane], ub0, ub1);
            upk2(pP2[32 + lane], pb0, pb1);
            part0 += ub0 * (0.5f * qb0 + pb0);
            part1 += ub1 * (0.5f * qb1 + pb1);
        }
#pragma unroll
        for (int o = 16; o; o >>= 1) {
            part0 += __shfl_xor_sync(0xffffffffu, part0, o);
            part1 += __shfl_xor_sync(0xffffffffu, part1, o);
        }
        if (lane == 0) {
            float u00, u01;
            upk2(pU2[0], u00, u01);
            out[pb] = part0;
            out[pb + 1] = part1;
            out[BATCH + pb] = u00;
            out[BATCH + pb + 1] = u01;
        }
    }
}

// ================= launch =================
extern "C" void kernel_launch(void* const* d_in, const int* in_sizes, int n_in,
                              void* d_out, int out_size) {
    const float* x  = (const float*)d_in[0];
    const float* W1 = (const float*)d_in[1];
    const float* b1 = (const float*)d_in[2];
    const float* W2 = (const float*)d_in[3];
    const float* b2 = (const float*)d_in[4];
    const float* L  = (const float*)d_in[5];
    const float* LP = (const float*)d_in[6];
    const float* LR = (const float*)d_in[7];
    const float* A  = (const float*)d_in[8];
    const float* Bm = (const float*)d_in[9];
    const float* u0 = (const float*)d_in[10];
    const float* s0 = (const float*)d_in[11];

    cudaFuncSetAttribute(ipm_kernel, cudaFuncAttributeMaxDynamicSharedMemorySize, SMEM_BYTES);

    setup_kernel<<<1, 128>>>(L, LP, LR, A, Bm, u0, s0);
    mlp_kernel<<<BATCH / 4, 128>>>(x, W1, b1, W2, b2);
    ipm_kernel<<<BATCH / PPC, NTH, SMEM_BYTES>>>((float*)d_out);
}

// round 16
// speedup vs baseline: 1.0199x; 1.0007x over previous
#include <cuda_runtime.h>
#include <math.h>

#define NIN   12
#define NOUT  4
#define NHID  512
#define NU    40
#define NB    108
#define NINEQ 148
#define BATCH 4096
#define IPM_ITERS 20
#define SIGMA 0.1f
#define BIGF  1000000000.0f
#define EPSF  0.0001f

#define WPB   8
#define PPW   2
#define PPC   (WPB * PPW)
#define NTH   (32 * WPB)

#define SKEW_STEP 1750          // dependent FMAs per warp-id step (~7K cycles)

// shared scalar layout (floats)
#define SQ_OFF 0                // 40*44 = 1760
#define SB_OFF 1760             // 108*44 = 4752
#define SH_OFF 6512             // 148 -> pad to 6672
#define PR_OFF 6672

// per-pair packed layout (u64 units)
#define H2_OFF   0              // 820 packed lower triangle
#define D2_OFF   820            // 148
#define V2_OFF   968            // 148
#define U2_OFF   1116           // 40
#define RHS2_OFF 1156           // 40
#define DU2_OFF  1196           // 40
#define LDI2_OFF 1236           // 40
#define P2_OFF   1276           // 40
#define PSTRIDE_U64 1320

#define SMEM_FLOATS (PR_OFF + WPB * PSTRIDE_U64 * 2)
#define SMEM_BYTES  (SMEM_FLOATS * 4)

typedef unsigned long long u64;

__device__ __forceinline__ u64 pk2(float lo, float hi) {
    u64 r; asm("mov.b64 %0,{%1,%2};" : "=l"(r) : "f"(lo), "f"(hi)); return r;
}
__device__ __forceinline__ void upk2(u64 v, float& lo, float& hi) {
    asm("mov.b64 {%0,%1},%2;" : "=f"(lo), "=f"(hi) : "l"(v));
}
__device__ __forceinline__ u64 rep2(float x) { return pk2(x, x); }
__device__ __forceinline__ u64 fma2(u64 a, u64 b, u64 c) {
    u64 d; asm("fma.rn.f32x2 %0,%1,%2,%3;" : "=l"(d) : "l"(a), "l"(b), "l"(c)); return d;
}
__device__ __forceinline__ u64 mul2(u64 a, u64 b) {
    u64 d; asm("mul.rn.f32x2 %0,%1,%2;" : "=l"(d) : "l"(a), "l"(b)); return d;
}
__device__ __forceinline__ u64 add2(u64 a, u64 b) {
    u64 d; asm("add.rn.f32x2 %0,%1,%2;" : "=l"(d) : "l"(a), "l"(b)); return d;
}
__device__ __forceinline__ u64 neg2(u64 a) { return a ^ 0x8000000080000000ULL; }

__device__ float g_Q[NU * NU];
__device__ float g_B[NB * NU];
__device__ float g_h[NINEQ];
__device__ float g_p[BATCH * NU];

__device__ __forceinline__ float lrelu(float x) { return x > 0.f ? x : 0.01f * x; }
__device__ __forceinline__ int toff(int r) { return (r * (r + 1)) >> 1; }

// ================= setup =================
__global__ void setup_kernel(const float* __restrict__ L, const float* __restrict__ LP,
                             const float* __restrict__ LR, const float* __restrict__ A,
                             const float* __restrict__ Bm, const float* __restrict__ u0,
                             const float* __restrict__ s0) {
    __shared__ float sQx[144], sP[144], sR[16], sBp[9 * 48];
    __shared__ float sBh[NB * NU];
    __shared__ float sM[NB * NU];
    int tid = threadIdx.x;
    const int NTs = 128;

    for (int idx = tid; idx < 144; idx += NTs) {
        int i = idx / 12, j = idx % 12;
        int mn = i < j ? i : j;
        float a = 0.f, b = 0.f;
        for (int k = 0; k <= mn; k++) {
            a += L[i * 12 + k] * L[j * 12 + k];
            b += LP[i * 12 + k] * LP[j * 12 + k];
        }
        sQx[idx] = a + (i == j ? EPSF : 0.f);
        sP[idx]  = b + (i == j ? EPSF : 0.f);
    }
    for (int idx = tid; idx < 16; idx += NTs) {
        int i = idx / 4, j = idx % 4;
        int mn = i < j ? i : j;
        float a = 0.f;
        for (int k = 0; k <= mn; k++) a += LR[i * 4 + k] * LR[j * 4 + k];
        sR[idx] = a + (i == j ? EPSF : 0.f);
    }
    if (tid < 48) sBp[tid] = Bm[tid];
    __syncthreads();

    for (int m = 1; m < 9; m++) {
        if (tid < 48) {
            int i = tid / 4, o = tid % 4;
            float v = 0.f;
            for (int k = 0; k < 12; k++) v += A[i * 12 + k] * sBp[(m - 1) * 48 + k * 4 + o];
            sBp[m * 48 + tid] = v;
        }
        __syncthreads();
    }

    for (int idx = tid; idx < NB * NU; idx += NTs) {
        int row = idx / NU, col = idx % NU;
        int rb = row / 12, i = row % 12, cb = col / 4, o = col % 4;
        float v = (cb <= rb) ? sBp[(rb - cb) * 48 + i * 4 + o] : 0.f;
        sBh[idx] = v;
        g_B[idx] = v;
    }
    __syncthreads();

    for (int idx = tid; idx < NB * NU; idx += NTs) {
        int row = idx / NU, col = idx % NU;
        int rb = row / 12, i = row % 12;
        const float* Qd = (rb < 8) ? sQx : sP;
        float a = 0.f;
        for (int k = 0; k < 12; k++) a += Qd[i * 12 + k] * sBh[(rb * 12 + k) * NU + col];
        sM[idx] = a;
    }
    __syncthreads();

    for (int idx = tid; idx < NU * NU; idx += NTs) {
        int a_ = idx / NU, b_ = idx % NU;
        float v = (a_ / 4 == b_ / 4) ? sR[(a_ % 4) * 4 + (b_ % 4)] : 0.f;
        for (int r = 0; r < NB; r++) v += sBh[r * NU + a_] * sM[r * NU + b_];
        g_Q[idx] = v;
    }

    for (int j = tid; j < NINEQ; j += NTs) {
        float v = s0[j];
        if (j < NU) v += u0[j];
        else {
            for (int i = 0; i < NU; i++) v += sBh[(j - NU) * NU + i] * u0[i];
        }
        g_h[j] = v;
    }
}

// ================= MLP =================
__global__ void mlp_kernel(const float* __restrict__ x, const float* __restrict__ W1,
                           const float* __restrict__ b1, const float* __restrict__ W2,
                           const float* __restrict__ b2) {
    __shared__ float hbuf[4][NHID];
    int warp = threadIdx.x >> 5, lane = threadIdx.x & 31;
    int row = blockIdx.x * 4 + warp;

    float xr[NIN];
#pragma unroll
    for (int c = 0; c < NIN; c++) xr[c] = x[row * NIN + c];

#pragma unroll
    for (int t = 0; t < NHID / 32; t++) {
        int j = lane + 32 * t;
        const float* w = W1 + j * NIN;
        float acc = b1[j];
#pragma unroll
        for (int c = 0; c < NIN; c++) acc += w[c] * xr[c];
        hbuf[warp][j] = lrelu(acc);
    }
    __syncwarp();

    for (int k = 0; k < NU; k++) {
        const float* w = W2 + k * NHID;
        float acc = 0.f;
#pragma unroll
        for (int t = 0; t < NHID / 32; t++) {
            int j = lane + 32 * t;
            acc += w[j] * hbuf[warp][j];
        }
#pragma unroll
        for (int o = 16; o; o >>= 1) acc += __shfl_xor_sync(0xffffffffu, acc, o);
        if (lane == 0) g_p[row * NU + k] = lrelu(acc + b2[k]);
    }
}

// ================= IPM: two problems per warp, f32x2, phase-skewed warps =================
__global__ void __launch_bounds__(NTH, 2) ipm_kernel(float* __restrict__ out) {
    extern __shared__ float sm[];
    float* sQ  = sm + SQ_OFF;    // stride 44
    float* sB  = sm + SB_OFF;    // stride 44
    float* sh_ = sm + SH_OFF;

    int tid = threadIdx.x;
    int lane = tid & 31, wid = tid >> 5;

    for (int idx = tid; idx < NU * NU; idx += NTH) sQ[(idx / NU) * 44 + idx % NU] = g_Q[idx];
    for (int idx = tid; idx < NB * NU; idx += NTH) sB[(idx / NU) * 44 + idx % NU] = g_B[idx];
    for (int idx = tid; idx < NINEQ; idx += NTH) sh_[idx] = g_h[idx];
    __syncthreads();

    // ---- phase skew: warp w starts ~w*7K cycles late so warps occupy different
    // phases of the iteration (breaks SM-wide lockstep through the serial
    // Cholesky/solve chains; fills issue slots during other warps' stalls) ----
    {
        float skf = (float)(wid + 1);
        int spin = wid * SKEW_STEP;
        for (int i = 0; i < spin; i++)
            asm volatile("fma.rn.f32 %0, %0, %1, %2;" : "+f"(skf) : "f"(0.9999f), "f"(1e-7f));
        if (skf == BIGF && lane == 63) out[0] = skf;  // never true; keeps chain live
    }

    int pb = blockIdx.x * PPC + wid * PPW;
    u64* PR = (u64*)(sm + PR_OFF) + wid * PSTRIDE_U64;
    u64* pH2  = PR + H2_OFF;
    u64* pD2  = PR + D2_OFF;
    u64* pV2  = PR + V2_OFF;
    u64* pU2  = PR + U2_OFF;
    u64* pR2  = PR + RHS2_OFF;
    u64* pDU2 = PR + DU2_OFF;
    u64* pLi2 = PR + LDI2_OFF;
    u64* pP2  = PR + P2_OFF;

    if (lane < NU) {
        pU2[lane] = 0ULL;
        pP2[lane] = pk2(g_p[pb * NU + lane], g_p[(pb + 1) * NU + lane]);
    }
    if (lane < 8) {
        pU2[32 + lane] = 0ULL;
        pP2[32 + lane] = pk2(g_p[pb * NU + 32 + lane], g_p[(pb + 1) * NU + 32 + lane]);
    }

    // per-lane scalar state; rp via exact recurrence rp_new = (1-alpha) * rp
    float rs0[5], rs1[5], rl0[5], rl1[5], rp0[5], rp1[5];
#pragma unroll
    for (int t = 0; t < 5; t++) {
        int j = lane + 32 * t;
        rs0[t] = rs1[t] = rl0[t] = rl1[t] = 1.f;
        float rpi = (j < NINEQ) ? (1.0f - sh_[j]) : 0.f;   // rp(0) = 1 - h
        rp0[t] = rpi; rp1[t] = rpi;
    }
    float mu0 = 1.0f, mu1 = 1.0f;

    // H 4x4 block-pair assignment (25 pairs + 5 singles, lanes 30,31 idle)
    int bi = 0, bkA = 0, bkB = 0;
    bool hasB = false, active = false;
    {
        int idx = 0;
        for (int r = 0; r < 10; r++) {
            int np = (r + 1) / 2;
            for (int q = 0; q < np; q++) {
                if (idx == lane) { bi = r; bkA = 2 * q; bkB = 2 * q + 1; hasB = true; active = true; }
                idx++;
            }
        }
        for (int r = 0; r < 10; r += 2) {
            if (idx == lane) { bi = r; bkA = r; bkB = r; hasB = false; active = true; }
            idx++;
        }
    }
    bool diagA = (bkA == bi);
    bool diagB = (bkB == bi);

    __syncwarp();

    for (int it = 0; it < IPM_ITERS; it++) {
        // ---- S0: d, v from register rp ----
#pragma unroll
        for (int t = 0; t < 5; t++) {
            int j = lane + 32 * t;
            if (j < NINEQ) {
                float ri0 = __fdividef(1.0f, rs0[t]);
                float ri1 = __fdividef(1.0f, rs1[t]);
                float d0 = rl0[t] * ri0, d1 = rl1[t] * ri1;
                pD2[j] = pk2(d0, d1);
                float v0 = SIGMA * mu0 * ri0 + d0 * rp0[t];
                float v1 = SIGMA * mu1 * ri1 + d1 * rp1[t];
                pV2[j] = pk2(v0, v1);
            }
        }
        __syncwarp();

        // ---- S1: H = Q + diag(d) + B^T diag(d) B ----
        {
            u64 acc0[4][4], acc1[4][4];
#pragma unroll
            for (int a = 0; a < 4; a++) {
                float4 v0 = *(const float4*)(sQ + (4 * bi + a) * 44 + 4 * bkA);
                acc0[a][0] = rep2(v0.x); acc0[a][1] = rep2(v0.y);
                acc0[a][2] = rep2(v0.z); acc0[a][3] = rep2(v0.w);
                float4 v1 = *(const float4*)(sQ + (4 * bi + a) * 44 + 4 * bkB);
                acc1[a][0] = rep2(v1.x); acc1[a][1] = rep2(v1.y);
                acc1[a][2] = rep2(v1.z); acc1[a][3] = rep2(v1.w);
            }
            if (diagA) {
#pragma unroll
                for (int a = 0; a < 4; a++) acc0[a][a] = add2(acc0[a][a], pD2[4 * bi + a]);
            }
            if (diagB) {
#pragma unroll
                for (int a = 0; a < 4; a++) acc1[a][a] = add2(acc1[a][a], pD2[4 * bi + a]);
            }
#pragma unroll 2
            for (int j = 0; j < NB; j++) {
                u64 dp = pD2[NU + j];
                const float* br = sB + j * 44;
                float4 gav = *(const float4*)(br + 4 * bi);
                float4 g0  = *(const float4*)(br + 4 * bkA);
                float4 g1  = *(const float4*)(br + 4 * bkB);
                u64 sa[4];
                sa[0] = mul2(dp, rep2(gav.x)); sa[1] = mul2(dp, rep2(gav.y));
                sa[2] = mul2(dp, rep2(gav.z)); sa[3] = mul2(dp, rep2(gav.w));
                u64 rb0[4] = {rep2(g0.x), rep2(g0.y), rep2(g0.z), rep2(g0.w)};
                u64 rb1[4] = {rep2(g1.x), rep2(g1.y), rep2(g1.z), rep2(g1.w)};
#pragma unroll
                for (int a = 0; a < 4; a++)
#pragma unroll
                    for (int c = 0; c < 4; c++) {
                        acc0[a][c] = fma2(sa[a], rb0[c], acc0[a][c]);
                        acc1[a][c] = fma2(sa[a], rb1[c], acc1[a][c]);
                    }
            }
            if (active) {
#pragma unroll
                for (int a = 0; a < 4; a++) {
                    int ob = toff(4 * bi + a);
#pragma unroll
                    for (int c = 0; c < 4; c++)
                        if (!diagA || c <= a) pH2[ob + 4 * bkA + c] = acc0[a][c];
                    if (hasB) {
#pragma unroll
                        for (int c = 0; c < 4; c++)
                            if (!diagB || c <= a) pH2[ob + 4 * bkB + c] = acc1[a][c];
                    }
                }
            }
        }

        // ---- rhs = -(Qu + p + v[:40] + B^T v[40:]) ----
        {
            u64 A0 = add2(pP2[lane], pV2[lane]);
            u64 A1 = (lane < 8) ? add2(pP2[32 + lane], pV2[32 + lane]) : 0ULL;
            const float4* q0 = (const float4*)(sQ + lane * 44);
            const float4* q1 = (const float4*)(sQ + (32 + lane) * 44);
#pragma unroll
            for (int q = 0; q < 10; q++) {
                float4 qv0 = q0[q];
                A0 = fma2(rep2(qv0.x), pU2[4 * q + 0], A0);
                A0 = fma2(rep2(qv0.y), pU2[4 * q + 1], A0);
                A0 = fma2(rep2(qv0.z), pU2[4 * q + 2], A0);
                A0 = fma2(rep2(qv0.w), pU2[4 * q + 3], A0);
                if (lane < 8) {
                    float4 qv1 = q1[q];
                    A1 = fma2(rep2(qv1.x), pU2[4 * q + 0], A1);
                    A1 = fma2(rep2(qv1.y), pU2[4 * q + 1], A1);
                    A1 = fma2(rep2(qv1.z), pU2[4 * q + 2], A1);
                    A1 = fma2(rep2(qv1.w), pU2[4 * q + 3], A1);
                }
            }
#pragma unroll 2
            for (int j = 0; j < NB; j++) {
                const float* br = sB + j * 44;
                A0 = fma2(rep2(br[lane]), pV2[NU + j], A0);
            }
            if (lane < 8) {
#pragma unroll
                for (int j = 96; j < NB; j++) {
                    const float* br = sB + j * 44;
                    A1 = fma2(rep2(br[32 + lane]), pV2[NU + j], A1);
                }
            }
            pR2[lane] = neg2(A0);
            if (lane < 8) pR2[32 + lane] = neg2(A1);
        }
        __syncwarp();

        // ---- S3: blocked Cholesky (panel=8), packed; 1 syncwarp per k ----
        for (int pp = 0; pp < 5; pp++) {
            int k0 = 8 * pp;
            for (int kk = 0; kk < 8; kk++) {
                int k = k0 + kk;
                int ok = toff(k);
                float h0, h1;
                upk2(pH2[ok + k], h0, h1);
                float i0 = rsqrtf(h0);
                float i1 = rsqrtf(h1);
                u64 ip = pk2(i0, i1);
                if (lane == 0) pLi2[k] = ip;
                int r0 = k + 1 + lane, r1 = r0 + 32;
                int or0 = toff(r0), or1 = toff(r1);
                u64 v0 = 0ULL, v1 = 0ULL;
                if (r0 < NU) { v0 = mul2(pH2[or0 + k], ip); pH2[or0 + k] = v0; }
                if (r1 < NU) { v1 = mul2(pH2[or1 + k], ip); pH2[or1 + k] = v1; }
                for (int j = k + 1; j < k0 + 8; j++) {
                    u64 m = __shfl_sync(0xffffffffu, v0, j - k - 1);
                    u64 nm = neg2(m);
                    if (r0 < NU && r0 >= j) pH2[or0 + j] = fma2(nm, v0, pH2[or0 + j]);
                    if (r1 < NU)            pH2[or1 + j] = fma2(nm, v1, pH2[or1 + j]);
                }
                __syncwarp();
            }
            if (pp < 4) {
                int base = k0 + 8;
                int nbk = (NU - base) >> 2;
                int cnt = nbk * (nbk + 1) / 2;
                for (int bb = lane; bb < cnt; bb += 32) {
                    int t = bb, r = 0;
                    while (t > r) { t -= r + 1; r++; }
                    int c = t;
                    int ri = base + 4 * r, ci = base + 4 * c;
                    bool diag = (r == c);
                    int oR[4], oC[4];
                    oR[0] = toff(ri);
                    oR[1] = oR[0] + ri + 1; oR[2] = oR[1] + ri + 2; oR[3] = oR[2] + ri + 3;
                    oC[0] = toff(ci);
                    oC[1] = oC[0] + ci + 1; oC[2] = oC[1] + ci + 2; oC[3] = oC[2] + ci + 3;
                    u64 a2[4][4];
#pragma unroll
                    for (int a = 0; a < 4; a++)
#pragma unroll
                        for (int cb = 0; cb < 4; cb++)
                            a2[a][cb] = pH2[oR[a] + ci + cb];
#pragma unroll
                    for (int kk = 0; kk < 8; kk++) {
                        u64 nla[4], lb[4];
#pragma unroll
                        for (int a = 0; a < 4; a++) nla[a] = neg2(pH2[oR[a] + k0 + kk]);
#pragma unroll
                        for (int cb = 0; cb < 4; cb++) lb[cb] = pH2[oC[cb] + k0 + kk];
#pragma unroll
                        for (int a = 0; a < 4; a++)
#pragma unroll
                            for (int cb = 0; cb < 4; cb++)
                                a2[a][cb] = fma2(nla[a], lb[cb], a2[a][cb]);
                    }
#pragma unroll
                    for (int a = 0; a < 4; a++)
#pragma unroll
                        for (int cb = 0; cb < 4; cb++)
                            if (!diag || cb <= a) pH2[oR[a] + ci + cb] = a2[a][cb];
                }
                __syncwarp();
            }
        }

        // ---- triangular solves (packed, fully unrolled) ----
        {
            int offL0 = toff(lane);
            int offL1 = toff(32 + lane);
            u64 a0 = pR2[lane];
            u64 a1 = (lane < 8) ? pR2[32 + lane] : 0ULL;
#pragma unroll
            for (int k = 0; k < NU; k++) {
                u64 src = (k < 32) ? a0 : a1;
                u64 y = mul2(__shfl_sync(0xffffffffu, src, k & 31), pLi2[k]);
                if (k < 32) { if (lane == k) a0 = y; }
                else        { if (lane == k - 32) a1 = y; }
                u64 ny = neg2(y);
                if (lane > k) a0 = fma2(pH2[offL0 + k], ny, a0);
                if (lane < 8 && 32 + lane > k) a1 = fma2(pH2[offL1 + k], ny, a1);
            }
#pragma unroll
            for (int k = NU - 1; k >= 0; k--) {
                const int offk = toff(k);
                u64 src = (k < 32) ? a0 : a1;
                u64 x = mul2(__shfl_sync(0xffffffffu, src, k & 31), pLi2[k]);
                if (k < 32) { if (lane == k) a0 = x; }
                else        { if (lane == k - 32) a1 = x; }
                u64 nx = neg2(x);
                if (lane < k) a0 = fma2(pH2[offk + lane], nx, a0);
                if (lane < 8 && 32 + lane < k) a1 = fma2(pH2[offk + 32 + lane], nx, a1);
            }
            pDU2[lane] = a0;
            if (lane < 8) pDU2[32 + lane] = a1;
        }
        __syncwarp();

        // ---- S4: ds, dlam, alpha ----
        float am0 = BIGF, am1 = BIGF;
        float ds0a[5], ds1a[5], dl0a[5], dl1a[5];
#pragma unroll
        for (int t = 0; t < 5; t++) {
            int j = lane + 32 * t;
            if (j < NINEQ) {
                u64 g;
                if (j < NU) g = pDU2[j];
                else {
                    const float4* br4 = (const float4*)(sB + (j - NU) * 44);
                    u64 acc = 0ULL;
                    const int bnd = (t == 1) ? 2 : (t == 2) ? 5 : (t == 3) ? 8 : 9;
#pragma unroll
                    for (int q = 0; q < bnd; q++) {
                        float4 bv = br4[q];
                        acc = fma2(rep2(bv.x), pDU2[4 * q + 0], acc);
                        acc = fma2(rep2(bv.y), pDU2[4 * q + 1], acc);
                        acc = fma2(rep2(bv.z), pDU2[4 * q + 2], acc);
                        acc = fma2(rep2(bv.w), pDU2[4 * q + 3], acc);
                    }
                    g = acc;
                }
                float g0, g1, d0, d1, v0, v1;
                upk2(g, g0, g1);
                upk2(pD2[j], d0, d1);
                upk2(pV2[j], v0, v1);
                float ds0 = -rp0[t] - g0, ds1 = -rp1[t] - g1;
                float dl0 = v0 - rl0[t] + d0 * g0;
                float dl1 = v1 - rl1[t] + d1 * g1;
                ds0a[t] = ds0; ds1a[t] = ds1; dl0a[t] = dl0; dl1a[t] = dl1;
                float q0 = (ds0 < 0.f) ? __fdividef(-rs0[t], ds0) : BIGF;
                float q1 = (dl0 < 0.f) ? __fdividef(-rl0[t], dl0) : BIGF;
                am0 = fminf(am0, fminf(q0, q1));
                float q2 = (ds1 < 0.f) ? __fdividef(-rs1[t], ds1) : BIGF;
                float q3 = (dl1 < 0.f) ? __fdividef(-rl1[t], dl1) : BIGF;
                am1 = fminf(am1, fminf(q2, q3));
            }
        }
#pragma unroll
        for (int o = 16; o; o >>= 1) {
            am0 = fminf(am0, __shfl_xor_sync(0xffffffffu, am0, o));
            am1 = fminf(am1, __shfl_xor_sync(0xffffffffu, am1, o));
        }
        float al0 = fminf(1.0f, 0.99f * am0);
        float al1 = fminf(1.0f, 0.99f * am1);

        // ---- S5: update + mu + rp recurrence ----
        float ls0 = 0.f, ls1 = 0.f;
        float om0 = 1.0f - al0, om1 = 1.0f - al1;
#pragma unroll
        for (int t = 0; t < 5; t++) {
            int j = lane + 32 * t;
            if (j < NINEQ) {
                rs0[t] += al0 * ds0a[t];  rl0[t] += al0 * dl0a[t];  ls0 += rs0[t] * rl0[t];
                rs1[t] += al1 * ds1a[t];  rl1[t] += al1 * dl1a[t];  ls1 += rs1[t] * rl1[t];
                rp0[t] *= om0;  rp1[t] *= om1;
            }
        }
#pragma unroll
        for (int o = 16; o; o >>= 1) {
            ls0 += __shfl_xor_sync(0xffffffffu, ls0, o);
            ls1 += __shfl_xor_sync(0xffffffffu, ls1, o);
        }
        mu0 = ls0 * (1.0f / 148.0f);
        mu1 = ls1 * (1.0f / 148.0f);

        u64 alp = pk2(al0, al1);
        pU2[lane] = fma2(alp, pDU2[lane], pU2[lane]);
        if (lane < 8) pU2[32 + lane] = fma2(alp, pDU2[32 + lane], pU2[32 + lane]);
        __syncwarp();
    }

    // ---- output: Q_value = 0.5 u'Qu + p'u ; u0 ----
    {
        const float4* q0 = (const float4*)(sQ + lane * 44);
        const float4* q1 = (const float4*)(sQ + (32 + lane) * 44);
        u64 qu0 = 0ULL, qu1 = 0ULL;
#pragma unroll
        for (int q = 0; q < 10; q++) {
            float4 qv0 = q0[q];
            qu0 = fma2(rep2(qv0.x), pU2[4 * q + 0], qu0);
            qu0 = fma2(rep2(qv0.y), pU2[4 * q + 1], qu0);
            qu0 = fma2(rep2(qv0.z), pU2[4 * q + 2], qu0);
            qu0 = fma2(rep2(qv0.w), pU2[4 * q + 3], qu0);
            if (lane < 8) {
                float4 qv1 = q1[q];
                qu1 = fma2(rep2(qv1.x), pU2[4 * q + 0], qu1);
                qu1 = fma2(rep2(qv1.y), pU2[4 * q + 1], qu1);
                qu1 = fma2(rep2(qv1.z), pU2[4 * q + 2], qu1);
                qu1 = fma2(rep2(qv1.w), pU2[4 * q + 3], qu1);
            }
        }
        float qa0, qa1, ua0, ua1, pa0, pa1;
        upk2(qu0, qa0, qa1);
        upk2(pU2[lane], ua0, ua1);
        upk2(pP2[lane], pa0, pa1);
        float part0 = ua0 * (0.5f * qa0 + pa0);
        float part1 = ua1 * (0.5f * qa1 + pa1);
        if (lane < 8) {
            float qb0, qb1, ub0, ub1, pb0, pb1;
            upk2(qu1, qb0, qb1);
            upk2(pU2[32 + lane], ub0, ub1);
            upk2(pP2[32 + lane], pb0, pb1);
            part0 += ub0 * (0.5f * qb0 + pb0);
            part1 += ub1 * (0.5f * qb1 + pb1);
        }
#pragma unroll
        for (int o = 16; o; o >>= 1) {
            part0 += __shfl_xor_sync(0xffffffffu, part0, o);
            part1 += __shfl_xor_sync(0xffffffffu, part1, o);
        }
        if (lane == 0) {
            float u00, u01;
            upk2(pU2[0], u00, u01);
            out[pb] = part0;
            out[pb + 1] = part1;
            out[BATCH + pb] = u00;
            out[BATCH + pb + 1] = u01;
        }
    }
}

// ================= launch =================
extern "C" void kernel_launch(void* const* d_in, const int* in_sizes, int n_in,
                              void* d_out, int out_size) {
    const float* x  = (const float*)d_in[0];
    const float* W1 = (const float*)d_in[1];
    const float* b1 = (const float*)d_in[2];
    const float* W2 = (const float*)d_in[3];
    const float* b2 = (const float*)d_in[4];
    const float* L  = (const float*)d_in[5];
    const float* LP = (const float*)d_in[6];
    const float* LR = (const float*)d_in[7];
    const float* A  = (const float*)d_in[8];
    const float* Bm = (const float*)d_in[9];
    const float* u0 = (const float*)d_in[10];
    const float* s0 = (const float*)d_in[11];

    cudaFuncSetAttribute(ipm_kernel, cudaFuncAttributeMaxDynamicSharedMemorySize, SMEM_BYTES);

    setup_kernel<<<1, 128>>>(L, LP, LR, A, Bm, u0, s0);
    mlp_kernel<<<BATCH / 4, 128>>>(x, W1, b1, W2, b2);
    ipm_kernel<<<BATCH / PPC, NTH, SMEM_BYTES>>>((float*)d_out);
}

// round 17
// speedup vs baseline: 1.0457x; 1.0253x over previous
#include <cuda_runtime.h>
#include <math.h>

#define NIN   12
#define NOUT  4
#define NHID  512
#define NU    40
#define NB    108
#define NINEQ 148
#define BATCH 4096
#define IPM_ITERS 20
#define SIGMA 0.1f
#define BIGF  1000000000.0f
#define EPSF  0.0001f

#define WPB   8
#define PPW   2
#define NTH   (32 * WPB)

// balanced grid: 296 CTAs = 2 x 148 SMs; 272 CTAs x 14 problems + 24 x 12 = 4096
#define GRID      296
#define NBIG      272
#define BIGCNT    14
#define SMALLCNT  12

// shared scalar layout (floats)
#define SQ_OFF 0                // 40*44 = 1760
#define SB_OFF 1760             // 108*44 = 4752
#define SH_OFF 6512             // 148 -> pad to 6672
#define PR_OFF 6672

// per-pair packed layout (u64 units)
#define H2_OFF   0              // 820 packed lower triangle
#define D2_OFF   820            // 148
#define V2_OFF   968            // 148
#define U2_OFF   1116           // 40
#define RHS2_OFF 1156           // 40
#define DU2_OFF  1196           // 40
#define LDI2_OFF 1236           // 40
#define P2_OFF   1276           // 40
#define PSTRIDE_U64 1320

#define SMEM_FLOATS (PR_OFF + WPB * PSTRIDE_U64 * 2)
#define SMEM_BYTES  (SMEM_FLOATS * 4)

typedef unsigned long long u64;

__device__ __forceinline__ u64 pk2(float lo, float hi) {
    u64 r; asm("mov.b64 %0,{%1,%2};" : "=l"(r) : "f"(lo), "f"(hi)); return r;
}
__device__ __forceinline__ void upk2(u64 v, float& lo, float& hi) {
    asm("mov.b64 {%0,%1},%2;" : "=f"(lo), "=f"(hi) : "l"(v));
}
__device__ __forceinline__ u64 rep2(float x) { return pk2(x, x); }
__device__ __forceinline__ u64 fma2(u64 a, u64 b, u64 c) {
    u64 d; asm("fma.rn.f32x2 %0,%1,%2,%3;" : "=l"(d) : "l"(a), "l"(b), "l"(c)); return d;
}
__device__ __forceinline__ u64 mul2(u64 a, u64 b) {
    u64 d; asm("mul.rn.f32x2 %0,%1,%2;" : "=l"(d) : "l"(a), "l"(b)); return d;
}
__device__ __forceinline__ u64 add2(u64 a, u64 b) {
    u64 d; asm("add.rn.f32x2 %0,%1,%2;" : "=l"(d) : "l"(a), "l"(b)); return d;
}
__device__ __forceinline__ u64 neg2(u64 a) { return a ^ 0x8000000080000000ULL; }

__device__ float g_Q[NU * NU];
__device__ float g_B[NB * NU];
__device__ float g_h[NINEQ];
__device__ float g_p[BATCH * NU];

__device__ __forceinline__ float lrelu(float x) { return x > 0.f ? x : 0.01f * x; }
__device__ __forceinline__ int toff(int r) { return (r * (r + 1)) >> 1; }

// ================= setup =================
__global__ void setup_kernel(const float* __restrict__ L, const float* __restrict__ LP,
                             const float* __restrict__ LR, const float* __restrict__ A,
                             const float* __restrict__ Bm, const float* __restrict__ u0,
                             const float* __restrict__ s0) {
    __shared__ float sQx[144], sP[144], sR[16], sBp[9 * 48];
    __shared__ float sBh[NB * NU];
    __shared__ float sM[NB * NU];
    int tid = threadIdx.x;
    const int NTs = 128;

    for (int idx = tid; idx < 144; idx += NTs) {
        int i = idx / 12, j = idx % 12;
        int mn = i < j ? i : j;
        float a = 0.f, b = 0.f;
        for (int k = 0; k <= mn; k++) {
            a += L[i * 12 + k] * L[j * 12 + k];
            b += LP[i * 12 + k] * LP[j * 12 + k];
        }
        sQx[idx] = a + (i == j ? EPSF : 0.f);
        sP[idx]  = b + (i == j ? EPSF : 0.f);
    }
    for (int idx = tid; idx < 16; idx += NTs) {
        int i = idx / 4, j = idx % 4;
        int mn = i < j ? i : j;
        float a = 0.f;
        for (int k = 0; k <= mn; k++) a += LR[i * 4 + k] * LR[j * 4 + k];
        sR[idx] = a + (i == j ? EPSF : 0.f);
    }
    if (tid < 48) sBp[tid] = Bm[tid];
    __syncthreads();

    for (int m = 1; m < 9; m++) {
        if (tid < 48) {
            int i = tid / 4, o = tid % 4;
            float v = 0.f;
            for (int k = 0; k < 12; k++) v += A[i * 12 + k] * sBp[(m - 1) * 48 + k * 4 + o];
            sBp[m * 48 + tid] = v;
        }
        __syncthreads();
    }

    for (int idx = tid; idx < NB * NU; idx += NTs) {
        int row = idx / NU, col = idx % NU;
        int rb = row / 12, i = row % 12, cb = col / 4, o = col % 4;
        float v = (cb <= rb) ? sBp[(rb - cb) * 48 + i * 4 + o] : 0.f;
        sBh[idx] = v;
        g_B[idx] = v;
    }
    __syncthreads();

    for (int idx = tid; idx < NB * NU; idx += NTs) {
        int row = idx / NU, col = idx % NU;
        int rb = row / 12, i = row % 12;
        const float* Qd = (rb < 8) ? sQx : sP;
        float a = 0.f;
        for (int k = 0; k < 12; k++) a += Qd[i * 12 + k] * sBh[(rb * 12 + k) * NU + col];
        sM[idx] = a;
    }
    __syncthreads();

    for (int idx = tid; idx < NU * NU; idx += NTs) {
        int a_ = idx / NU, b_ = idx % NU;
        float v = (a_ / 4 == b_ / 4) ? sR[(a_ % 4) * 4 + (b_ % 4)] : 0.f;
        for (int r = 0; r < NB; r++) v += sBh[r * NU + a_] * sM[r * NU + b_];
        g_Q[idx] = v;
    }

    for (int j = tid; j < NINEQ; j += NTs) {
        float v = s0[j];
        if (j < NU) v += u0[j];
        else {
            for (int i = 0; i < NU; i++) v += sBh[(j - NU) * NU + i] * u0[i];
        }
        g_h[j] = v;
    }
}

// ================= MLP =================
__global__ void mlp_kernel(const float* __restrict__ x, const float* __restrict__ W1,
                           const float* __restrict__ b1, const float* __restrict__ W2,
                           const float* __restrict__ b2) {
    __shared__ float hbuf[4][NHID];
    int warp = threadIdx.x >> 5, lane = threadIdx.x & 31;
    int row = blockIdx.x * 4 + warp;

    float xr[NIN];
#pragma unroll
    for (int c = 0; c < NIN; c++) xr[c] = x[row * NIN + c];

#pragma unroll
    for (int t = 0; t < NHID / 32; t++) {
        int j = lane + 32 * t;
        const float* w = W1 + j * NIN;
        float acc = b1[j];
#pragma unroll
        for (int c = 0; c < NIN; c++) acc += w[c] * xr[c];
        hbuf[warp][j] = lrelu(acc);
    }
    __syncwarp();

    for (int k = 0; k < NU; k++) {
        const float* w = W2 + k * NHID;
        float acc = 0.f;
#pragma unroll
        for (int t = 0; t < NHID / 32; t++) {
            int j = lane + 32 * t;
            acc += w[j] * hbuf[warp][j];
        }
#pragma unroll
        for (int o = 16; o; o >>= 1) acc += __shfl_xor_sync(0xffffffffu, acc, o);
        if (lane == 0) g_p[row * NU + k] = lrelu(acc + b2[k]);
    }
}

// ================= IPM: two problems per warp, f32x2, balanced 296-CTA grid =================
__global__ void __launch_bounds__(NTH, 2) ipm_kernel(float* __restrict__ out) {
    extern __shared__ float sm[];
    float* sQ  = sm + SQ_OFF;    // stride 44
    float* sB  = sm + SB_OFF;    // stride 44
    float* sh_ = sm + SH_OFF;

    int tid = threadIdx.x;
    int lane = tid & 31, wid = tid >> 5;

    for (int idx = tid; idx < NU * NU; idx += NTH) sQ[(idx / NU) * 44 + idx % NU] = g_Q[idx];
    for (int idx = tid; idx < NB * NU; idx += NTH) sB[(idx / NU) * 44 + idx % NU] = g_B[idx];
    for (int idx = tid; idx < NINEQ; idx += NTH) sh_[idx] = g_h[idx];
    __syncthreads();

    // balanced problem assignment: CTA < NBIG gets BIGCNT problems, else SMALLCNT
    int bx = blockIdx.x;
    int cstart = (bx < NBIG) ? (bx * BIGCNT) : (NBIG * BIGCNT + (bx - NBIG) * SMALLCNT);
    int ccnt   = (bx < NBIG) ? BIGCNT : SMALLCNT;
    if (wid * PPW >= ccnt) return;   // idle warps exit (no block syncs after this)
    int pb = cstart + wid * PPW;

    u64* PR = (u64*)(sm + PR_OFF) + wid * PSTRIDE_U64;
    u64* pH2  = PR + H2_OFF;
    u64* pD2  = PR + D2_OFF;
    u64* pV2  = PR + V2_OFF;
    u64* pU2  = PR + U2_OFF;
    u64* pR2  = PR + RHS2_OFF;
    u64* pDU2 = PR + DU2_OFF;
    u64* pLi2 = PR + LDI2_OFF;
    u64* pP2  = PR + P2_OFF;

    if (lane < NU) {
        pU2[lane] = 0ULL;
        pP2[lane] = pk2(g_p[pb * NU + lane], g_p[(pb + 1) * NU + lane]);
    }
    if (lane < 8) {
        pU2[32 + lane] = 0ULL;
        pP2[32 + lane] = pk2(g_p[pb * NU + 32 + lane], g_p[(pb + 1) * NU + 32 + lane]);
    }

    // per-lane scalar state; rp via exact recurrence rp_new = (1-alpha) * rp
    float rs0[5], rs1[5], rl0[5], rl1[5], rp0[5], rp1[5];
#pragma unroll
    for (int t = 0; t < 5; t++) {
        int j = lane + 32 * t;
        rs0[t] = rs1[t] = rl0[t] = rl1[t] = 1.f;
        float rpi = (j < NINEQ) ? (1.0f - sh_[j]) : 0.f;   // rp(0) = G*0 + s0 - h = 1 - h
        rp0[t] = rpi; rp1[t] = rpi;
    }
    float mu0 = 1.0f, mu1 = 1.0f;

    // H 4x4 block-pair assignment (25 pairs + 5 singles, lanes 30,31 idle)
    int bi = 0, bkA = 0, bkB = 0;
    bool hasB = false, active = false;
    {
        int idx = 0;
        for (int r = 0; r < 10; r++) {
            int np = (r + 1) / 2;
            for (int q = 0; q < np; q++) {
                if (idx == lane) { bi = r; bkA = 2 * q; bkB = 2 * q + 1; hasB = true; active = true; }
                idx++;
            }
        }
        for (int r = 0; r < 10; r += 2) {
            if (idx == lane) { bi = r; bkA = r; bkB = r; hasB = false; active = true; }
            idx++;
        }
    }
    bool diagA = (bkA == bi);
    bool diagB = (bkB == bi);

    __syncwarp();

    for (int it = 0; it < IPM_ITERS; it++) {
        // ---- S0: d, v from register rp ----
#pragma unroll
        for (int t = 0; t < 5; t++) {
            int j = lane + 32 * t;
            if (j < NINEQ) {
                float ri0 = __fdividef(1.0f, rs0[t]);
                float ri1 = __fdividef(1.0f, rs1[t]);
                float d0 = rl0[t] * ri0, d1 = rl1[t] * ri1;
                pD2[j] = pk2(d0, d1);
                float v0 = SIGMA * mu0 * ri0 + d0 * rp0[t];
                float v1 = SIGMA * mu1 * ri1 + d1 * rp1[t];
                pV2[j] = pk2(v0, v1);
            }
        }
        __syncwarp();

        // ---- S1: H = Q + diag(d) + B^T diag(d) B ----
        {
            u64 acc0[4][4], acc1[4][4];
#pragma unroll
            for (int a = 0; a < 4; a++) {
                float4 v0 = *(const float4*)(sQ + (4 * bi + a) * 44 + 4 * bkA);
                acc0[a][0] = rep2(v0.x); acc0[a][1] = rep2(v0.y);
                acc0[a][2] = rep2(v0.z); acc0[a][3] = rep2(v0.w);
                float4 v1 = *(const float4*)(sQ + (4 * bi + a) * 44 + 4 * bkB);
                acc1[a][0] = rep2(v1.x); acc1[a][1] = rep2(v1.y);
                acc1[a][2] = rep2(v1.z); acc1[a][3] = rep2(v1.w);
            }
            if (diagA) {
#pragma unroll
                for (int a = 0; a < 4; a++) acc0[a][a] = add2(acc0[a][a], pD2[4 * bi + a]);
            }
            if (diagB) {
#pragma unroll
                for (int a = 0; a < 4; a++) acc1[a][a] = add2(acc1[a][a], pD2[4 * bi + a]);
            }
#pragma unroll 2
            for (int j = 0; j < NB; j++) {
                u64 dp = pD2[NU + j];
                const float* br = sB + j * 44;
                float4 gav = *(const float4*)(br + 4 * bi);
                float4 g0  = *(const float4*)(br + 4 * bkA);
                float4 g1  = *(const float4*)(br + 4 * bkB);
                u64 sa[4];
                sa[0] = mul2(dp, rep2(gav.x)); sa[1] = mul2(dp, rep2(gav.y));
                sa[2] = mul2(dp, rep2(gav.z)); sa[3] = mul2(dp, rep2(gav.w));
                u64 rb0[4] = {rep2(g0.x), rep2(g0.y), rep2(g0.z), rep2(g0.w)};
                u64 rb1[4] = {rep2(g1.x), rep2(g1.y), rep2(g1.z), rep2(g1.w)};
#pragma unroll
                for (int a = 0; a < 4; a++)
#pragma unroll
                    for (int c = 0; c < 4; c++) {
                        acc0[a][c] = fma2(sa[a], rb0[c], acc0[a][c]);
                        acc1[a][c] = fma2(sa[a], rb1[c], acc1[a][c]);
                    }
            }
            if (active) {
#pragma unroll
                for (int a = 0; a < 4; a++) {
                    int ob = toff(4 * bi + a);
#pragma unroll
                    for (int c = 0; c < 4; c++)
                        if (!diagA || c <= a) pH2[ob + 4 * bkA + c] = acc0[a][c];
                    if (hasB) {
#pragma unroll
                        for (int c = 0; c < 4; c++)
                            if (!diagB || c <= a) pH2[ob + 4 * bkB + c] = acc1[a][c];
                    }
                }
            }
        }

        // ---- rhs = -(Qu + p + v[:40] + B^T v[40:]) ----
        {
            u64 A0 = add2(pP2[lane], pV2[lane]);
            u64 A1 = (lane < 8) ? add2(pP2[32 + lane], pV2[32 + lane]) : 0ULL;
            const float4* q0 = (const float4*)(sQ + lane * 44);
            const float4* q1 = (const float4*)(sQ + (32 + lane) * 44);
#pragma unroll
            for (int q = 0; q < 10; q++) {
                float4 qv0 = q0[q];
                A0 = fma2(rep2(qv0.x), pU2[4 * q + 0], A0);
                A0 = fma2(rep2(qv0.y), pU2[4 * q + 1], A0);
                A0 = fma2(rep2(qv0.z), pU2[4 * q + 2], A0);
                A0 = fma2(rep2(qv0.w), pU2[4 * q + 3], A0);
                if (lane < 8) {
                    float4 qv1 = q1[q];
                    A1 = fma2(rep2(qv1.x), pU2[4 * q + 0], A1);
                    A1 = fma2(rep2(qv1.y), pU2[4 * q + 1], A1);
                    A1 = fma2(rep2(qv1.z), pU2[4 * q + 2], A1);
                    A1 = fma2(rep2(qv1.w), pU2[4 * q + 3], A1);
                }
            }
#pragma unroll 2
            for (int j = 0; j < NB; j++) {
                const float* br = sB + j * 44;
                A0 = fma2(rep2(br[lane]), pV2[NU + j], A0);
            }
            if (lane < 8) {
#pragma unroll
                for (int j = 96; j < NB; j++) {
                    const float* br = sB + j * 44;
                    A1 = fma2(rep2(br[32 + lane]), pV2[NU + j], A1);
                }
            }
            pR2[lane] = neg2(A0);
            if (lane < 8) pR2[32 + lane] = neg2(A1);
        }
        __syncwarp();

        // ---- S3: blocked Cholesky (panel=8), packed; 1 syncwarp per k ----
        for (int pp = 0; pp < 5; pp++) {
            int k0 = 8 * pp;
            for (int kk = 0; kk < 8; kk++) {
                int k = k0 + kk;
                int ok = toff(k);
                float h0, h1;
                upk2(pH2[ok + k], h0, h1);
                float i0 = rsqrtf(h0);
                float i1 = rsqrtf(h1);
                u64 ip = pk2(i0, i1);
                if (lane == 0) pLi2[k] = ip;
                int r0 = k + 1 + lane, r1 = r0 + 32;
                int or0 = toff(r0), or1 = toff(r1);
                u64 v0 = 0ULL, v1 = 0ULL;
                if (r0 < NU) { v0 = mul2(pH2[or0 + k], ip); pH2[or0 + k] = v0; }
                if (r1 < NU) { v1 = mul2(pH2[or1 + k], ip); pH2[or1 + k] = v1; }
                for (int j = k + 1; j < k0 + 8; j++) {
                    u64 m = __shfl_sync(0xffffffffu, v0, j - k - 1);
                    u64 nm = neg2(m);
                    if (r0 < NU && r0 >= j) pH2[or0 + j] = fma2(nm, v0, pH2[or0 + j]);
                    if (r1 < NU)            pH2[or1 + j] = fma2(nm, v1, pH2[or1 + j]);
                }
                __syncwarp();
            }
            if (pp < 4) {
                int base = k0 + 8;
                int nbk = (NU - base) >> 2;
                int cnt = nbk * (nbk + 1) / 2;
                for (int bb = lane; bb < cnt; bb += 32) {
                    int t = bb, r = 0;
                    while (t > r) { t -= r + 1; r++; }
                    int c = t;
                    int ri = base + 4 * r, ci = base + 4 * c;
                    bool diag = (r == c);
                    int oR[4], oC[4];
                    oR[0] = toff(ri);
                    oR[1] = oR[0] + ri + 1; oR[2] = oR[1] + ri + 2; oR[3] = oR[2] + ri + 3;
                    oC[0] = toff(ci);
                    oC[1] = oC[0] + ci + 1; oC[2] = oC[1] + ci + 2; oC[3] = oC[2] + ci + 3;
                    u64 a2[4][4];
#pragma unroll
                    for (int a = 0; a < 4; a++)
#pragma unroll
                        for (int cb = 0; cb < 4; cb++)
                            a2[a][cb] = pH2[oR[a] + ci + cb];
#pragma unroll
                    for (int kk = 0; kk < 8; kk++) {
                        u64 nla[4], lb[4];
#pragma unroll
                        for (int a = 0; a < 4; a++) nla[a] = neg2(pH2[oR[a] + k0 + kk]);
#pragma unroll
                        for (int cb = 0; cb < 4; cb++) lb[cb] = pH2[oC[cb] + k0 + kk];
#pragma unroll
                        for (int a = 0; a < 4; a++)
#pragma unroll
                            for (int cb = 0; cb < 4; cb++)
                                a2[a][cb] = fma2(nla[a], lb[cb], a2[a][cb]);
                    }
#pragma unroll
                    for (int a = 0; a < 4; a++)
#pragma unroll
                        for (int cb = 0; cb < 4; cb++)
                            if (!diag || cb <= a) pH2[oR[a] + ci + cb] = a2[a][cb];
                }
                __syncwarp();
            }
        }

        // ---- triangular solves (packed, fully unrolled) ----
        {
            int offL0 = toff(lane);
            int offL1 = toff(32 + lane);
            u64 a0 = pR2[lane];
            u64 a1 = (lane < 8) ? pR2[32 + lane] : 0ULL;
#pragma unroll
            for (int k = 0; k < NU; k++) {
                u64 src = (k < 32) ? a0 : a1;
                u64 y = mul2(__shfl_sync(0xffffffffu, src, k & 31), pLi2[k]);
                if (k < 32) { if (lane == k) a0 = y; }
                else        { if (lane == k - 32) a1 = y; }
                u64 ny = neg2(y);
                if (lane > k) a0 = fma2(pH2[offL0 + k], ny, a0);
                if (lane < 8 && 32 + lane > k) a1 = fma2(pH2[offL1 + k], ny, a1);
            }
#pragma unroll
            for (int k = NU - 1; k >= 0; k--) {
                const int offk = toff(k);
                u64 src = (k < 32) ? a0 : a1;
                u64 x = mul2(__shfl_sync(0xffffffffu, src, k & 31), pLi2[k]);
                if (k < 32) { if (lane == k) a0 = x; }
                else        { if (lane == k - 32) a1 = x; }
                u64 nx = neg2(x);
                if (lane < k) a0 = fma2(pH2[offk + lane], nx, a0);
                if (lane < 8 && 32 + lane < k) a1 = fma2(pH2[offk + 32 + lane], nx, a1);
            }
            pDU2[lane] = a0;
            if (lane < 8) pDU2[32 + lane] = a1;
        }
        __syncwarp();

        // ---- S4: ds, dlam, alpha ----
        float am0 = BIGF, am1 = BIGF;
        float ds0a[5], ds1a[5], dl0a[5], dl1a[5];
#pragma unroll
        for (int t = 0; t < 5; t++) {
            int j = lane + 32 * t;
            if (j < NINEQ) {
                u64 g;
                if (j < NU) g = pDU2[j];
                else {
                    const float4* br4 = (const float4*)(sB + (j - NU) * 44);
                    u64 acc = 0ULL;
                    const int bnd = (t == 1) ? 2 : (t == 2) ? 5 : (t == 3) ? 8 : 9;
#pragma unroll
                    for (int q = 0; q < bnd; q++) {
                        float4 bv = br4[q];
                        acc = fma2(rep2(bv.x), pDU2[4 * q + 0], acc);
                        acc = fma2(rep2(bv.y), pDU2[4 * q + 1], acc);
                        acc = fma2(rep2(bv.z), pDU2[4 * q + 2], acc);
                        acc = fma2(rep2(bv.w), pDU2[4 * q + 3], acc);
                    }
                    g = acc;
                }
                float g0, g1, d0, d1, v0, v1;
                upk2(g, g0, g1);
                upk2(pD2[j], d0, d1);
                upk2(pV2[j], v0, v1);
                float ds0 = -rp0[t] - g0, ds1 = -rp1[t] - g1;
                float dl0 = v0 - rl0[t] + d0 * g0;
                float dl1 = v1 - rl1[t] + d1 * g1;
                ds0a[t] = ds0; ds1a[t] = ds1; dl0a[t] = dl0; dl1a[t] = dl1;
                float q0 = (ds0 < 0.f) ? __fdividef(-rs0[t], ds0) : BIGF;
                float q1 = (dl0 < 0.f) ? __fdividef(-rl0[t], dl0) : BIGF;
                am0 = fminf(am0, fminf(q0, q1));
                float q2 = (ds1 < 0.f) ? __fdividef(-rs1[t], ds1) : BIGF;
                float q3 = (dl1 < 0.f) ? __fdividef(-rl1[t], dl1) : BIGF;
                am1 = fminf(am1, fminf(q2, q3));
            }
        }
#pragma unroll
        for (int o = 16; o; o >>= 1) {
            am0 = fminf(am0, __shfl_xor_sync(0xffffffffu, am0, o));
            am1 = fminf(am1, __shfl_xor_sync(0xffffffffu, am1, o));
        }
        float al0 = fminf(1.0f, 0.99f * am0);
        float al1 = fminf(1.0f, 0.99f * am1);

        // ---- S5: update + mu + rp recurrence ----
        float ls0 = 0.f, ls1 = 0.f;
        float om0 = 1.0f - al0, om1 = 1.0f - al1;
#pragma unroll
        for (int t = 0; t < 5; t++) {
            int j = lane + 32 * t;
            if (j < NINEQ) {
                rs0[t] += al0 * ds0a[t];  rl0[t] += al0 * dl0a[t];  ls0 += rs0[t] * rl0[t];
                rs1[t] += al1 * ds1a[t];  rl1[t] += al1 * dl1a[t];  ls1 += rs1[t] * rl1[t];
                rp0[t] *= om0;  rp1[t] *= om1;
            }
        }
#pragma unroll
        for (int o = 16; o; o >>= 1) {
            ls0 += __shfl_xor_sync(0xffffffffu, ls0, o);
            ls1 += __shfl_xor_sync(0xffffffffu, ls1, o);
        }
        mu0 = ls0 * (1.0f / 148.0f);
        mu1 = ls1 * (1.0f / 148.0f);

        u64 alp = pk2(al0, al1);
        pU2[lane] = fma2(alp, pDU2[lane], pU2[lane]);
        if (lane < 8) pU2[32 + lane] = fma2(alp, pDU2[32 + lane], pU2[32 + lane]);
        __syncwarp();
    }

    // ---- output: Q_value = 0.5 u'Qu + p'u ; u0 ----
    {
        const float4* q0 = (const float4*)(sQ + lane * 44);
        const float4* q1 = (const float4*)(sQ + (32 + lane) * 44);
        u64 qu0 = 0ULL, qu1 = 0ULL;
#pragma unroll
        for (int q = 0; q < 10; q++) {
            float4 qv0 = q0[q];
            qu0 = fma2(rep2(qv0.x), pU2[4 * q + 0], qu0);
            qu0 = fma2(rep2(qv0.y), pU2[4 * q + 1], qu0);
            qu0 = fma2(rep2(qv0.z), pU2[4 * q + 2], qu0);
            qu0 = fma2(rep2(qv0.w), pU2[4 * q + 3], qu0);
            if (lane < 8) {
                float4 qv1 = q1[q];
                qu1 = fma2(rep2(qv1.x), pU2[4 * q + 0], qu1);
                qu1 = fma2(rep2(qv1.y), pU2[4 * q + 1], qu1);
                qu1 = fma2(rep2(qv1.z), pU2[4 * q + 2], qu1);
                qu1 = fma2(rep2(qv1.w), pU2[4 * q + 3], qu1);
            }
        }
        float qa0, qa1, ua0, ua1, pa0, pa1;
        upk2(qu0, qa0, qa1);
        upk2(pU2[lane], ua0, ua1);
        upk2(pP2[lane], pa0, pa1);
        float part0 = ua0 * (0.5f * qa0 + pa0);
        float part1 = ua1 * (0.5f * qa1 + pa1);
        if (lane < 8) {
            float qb0, qb1, ub0, ub1, pb0, pb1;
            upk2(qu1, qb0, qb1);
            upk2(pU2[32 + lane], ub0, ub1);
            upk2(pP2[32 + lane], pb0, pb1);
            part0 += ub0 * (0.5f * qb0 + pb0);
            part1 += ub1 * (0.5f * qb1 + pb1);
        }
#pragma unroll
        for (int o = 16; o; o >>= 1) {
            part0 += __shfl_xor_sync(0xffffffffu, part0, o);
            part1 += __shfl_xor_sync(0xffffffffu, part1, o);
        }
        if (lane == 0) {
            float u00, u01;
            upk2(pU2[0], u00, u01);
            out[pb] = part0;
            out[pb + 1] = part1;
            out[BATCH + pb] = u00;
            out[BATCH + pb + 1] = u01;
        }
    }
}

// ================= launch =================
extern "C" void kernel_launch(void* const* d_in, const int* in_sizes, int n_in,
                              void* d_out, int out_size) {
    const float* x  = (const float*)d_in[0];
    const float* W1 = (const float*)d_in[1];
    const float* b1 = (const float*)d_in[2];
    const float* W2 = (const float*)d_in[3];
    const float* b2 = (const float*)d_in[4];
    const float* L  = (const float*)d_in[5];
    const float* LP = (const float*)d_in[6];
    const float* LR = (const float*)d_in[7];
    const float* A  = (const float*)d_in[8];
    const float* Bm = (const float*)d_in[9];
    const float* u0 = (const float*)d_in[10];
    const float* s0 = (const float*)d_in[11];

    cudaFuncSetAttribute(ipm_kernel, cudaFuncAttributeMaxDynamicSharedMemorySize, SMEM_BYTES);

    setup_kernel<<<1, 128>>>(L, LP, LR, A, Bm, u0, s0);
    mlp_kernel<<<BATCH / 4, 128>>>(x, W1, b1, W2, b2);
    ipm_kernel<<<GRID, NTH, SMEM_BYTES>>>((float*)d_out);
}